// round 3
// baseline (speedup 1.0000x reference)
#include <cuda_runtime.h>
#include <math.h>

#define DIMC    1024
#define BATCH   4
#define TQ      1024
#define HEADS   16
#define HD      64
#define KADA    320
#define KTSK    512
#define NQROWS  (BATCH*TQ)     /* 4096 */
#define NADROWS (BATCH*KADA)   /* 1280 */
#define NTKROWS (BATCH*KTSK)   /* 2048 */
#define NTILES  29             /* 16 tok + 5 ada + 8 tsk, 64 keys each = 1856 */

// ---------------- scratch (device globals; no runtime allocation) ----------------
__device__ float g_q   [NQROWS * DIMC];
__device__ float g_ktok[NQROWS * DIMC];
__device__ float g_vtok[NQROWS * DIMC];
__device__ float g_had [NADROWS * DIMC];
__device__ float g_kada[NADROWS * DIMC];
__device__ float g_vada[NADROWS * DIMC];
__device__ float g_ktsk[NTKROWS * DIMC];
__device__ float g_vtsk[NTKROWS * DIMC];
__device__ float g_attn[NQROWS * DIMC];
__device__ float g_y   [NQROWS * DIMC];
__device__ float g_yln [NQROWS * DIMC];

// ---------------- h_adapter = concat(h_a, p) along seq ----------------
__global__ void concat_kernel(const float* __restrict__ ha,
                              const float* __restrict__ pp,
                              float* __restrict__ out)
{
    int idx = blockIdx.x * blockDim.x + threadIdx.x;     // float4 index
    const int C4 = DIMC / 4;
    const int total = NADROWS * C4;
    if (idx >= total) return;
    int c4  = idx % C4;
    int row = idx / C4;
    int b = row / KADA;
    int s = row % KADA;
    float4 v;
    if (s < 256) v = ((const float4*)ha)[(size_t)(b * 256 + s) * C4 + c4];
    else         v = ((const float4*)pp)[(size_t)(b * 64 + (s - 256)) * C4 + c4];
    ((float4*)out)[idx] = v;
}

// ---------------- SGEMM: C = A[MxK] @ W[KxN] + bias (+res) (rope/relu epilogue) --
// 64x64 block tile, BK=16, 256 threads, 4x4 micro-tile.
__global__ __launch_bounds__(256)
void sgemm_kernel(const float* __restrict__ A, const float* __restrict__ W,
                  const float* __restrict__ bias, const float* __restrict__ res,
                  float* __restrict__ C, int M, int K, int N,
                  int rope_seq, int do_relu)
{
    __shared__ float As[16 * 68];   // transposed: As[k][m], pitch 68 (float4-aligned)
    __shared__ float Bs[16 * 64];   // Bs[k][n]

    const int tid = threadIdx.x;
    const int tx = tid & 15, ty = tid >> 4;
    const int bm = blockIdx.y * 64, bn = blockIdx.x * 64;
    const int aRow = tid >> 2,  aK   = (tid & 3)  << 2;
    const int bRow = tid >> 4,  bCol = (tid & 15) << 2;
    const float* Aptr = A + (size_t)(bm + aRow) * K + aK;
    const float* Wptr = W + (size_t)bRow * N + bn + bCol;

    float acc[4][4] = {};

    for (int k0 = 0; k0 < K; k0 += 16) {
        float4 a4 = *(const float4*)(Aptr + k0);
        float4 b4 = *(const float4*)(Wptr + (size_t)k0 * N);
        As[(aK + 0) * 68 + aRow] = a4.x;
        As[(aK + 1) * 68 + aRow] = a4.y;
        As[(aK + 2) * 68 + aRow] = a4.z;
        As[(aK + 3) * 68 + aRow] = a4.w;
        *(float4*)&Bs[bRow * 64 + bCol] = b4;
        __syncthreads();
#pragma unroll
        for (int k = 0; k < 16; k++) {
            float4 av = *(const float4*)&As[k * 68 + ty * 4];
            float4 bv = *(const float4*)&Bs[k * 64 + tx * 4];
            float a[4] = {av.x, av.y, av.z, av.w};
            float b[4] = {bv.x, bv.y, bv.z, bv.w};
#pragma unroll
            for (int i = 0; i < 4; i++)
#pragma unroll
                for (int j = 0; j < 4; j++)
                    acc[i][j] = fmaf(a[i], b[j], acc[i][j]);
        }
        __syncthreads();
    }

    // epilogue
    const int gCol0 = bn + tx * 4;
#pragma unroll
    for (int i = 0; i < 4; i++) {
        const int gRow = bm + ty * 4 + i;
        float v[4];
#pragma unroll
        for (int j = 0; j < 4; j++) v[j] = acc[i][j] + bias[gCol0 + j];
        if (res) {
            const float* rr = res + (size_t)gRow * N + gCol0;
#pragma unroll
            for (int j = 0; j < 4; j++) v[j] += rr[j];
        }
        if (rope_seq) {
            const int pos = gRow % rope_seq;
            const float fp = (float)pos;
#pragma unroll
            for (int j = 0; j < 4; j += 2) {
                // d even always (gCol0 multiple of 4, j even)
                int d  = (gCol0 + j) & 63;
                int f0 = d & 31;                  // concat tables: freq idx = d % 32
                float inv0 = exp2f((float)f0       * -0.41524101186409203f);
                float inv1 = exp2f((float)(f0 + 1) * -0.41524101186409203f);
                float s0, c0, s1, c1;
                sincosf(fp * inv0, &s0, &c0);
                sincosf(fp * inv1, &s1, &c1);
                float e = v[j], o = v[j + 1];
                // rotate_half: rh[2i] = -x[2i+1], rh[2i+1] = x[2i]
                v[j]     = e * c0 - o * s0;
                v[j + 1] = o * c1 + e * s1;
            }
        }
        if (do_relu) {
#pragma unroll
            for (int j = 0; j < 4; j++) v[j] = fmaxf(v[j], 0.0f);
        }
        float4 o4 = make_float4(v[0], v[1], v[2], v[3]);
        *(float4*)(C + (size_t)gRow * N + gCol0) = o4;
    }
}

// ---------------- flash attention over 3 concatenated KV sources ----------------
// Block = (qtile, head, batch); 64 q rows, 64-key tiles, online softmax.
__global__ __launch_bounds__(256)
void attn_kernel(const float* __restrict__ q,
                 const float* __restrict__ ktok, const float* __restrict__ vtok,
                 const float* __restrict__ kada, const float* __restrict__ vada,
                 const float* __restrict__ ktsk, const float* __restrict__ vtsk,
                 const float* __restrict__ gate, float* __restrict__ out)
{
    extern __shared__ float sm[];
    float* Qst  = sm;                 // [d][q]   64x65
    float* Kst  = Qst + 64 * 65;      // [d][key] 64x65
    float* Vs   = Kst + 64 * 65;      // [key][d] 64x65
    float* Sst  = Vs  + 64 * 65;      // [key][q] 64x65
    float* sm_m = Sst + 64 * 65;      // 64
    float* sm_l = sm_m + 64;          // 64
    float* sm_a = sm_l + 64;          // 64
    float* red  = sm_a + 64;          // 256

    const int b = blockIdx.z, h = blockIdx.y, qt = blockIdx.x;
    const int tid = threadIdx.x;
    const int tx = tid & 15, ty = tid >> 4;
    const float gfac = tanhf(gate[0]);

    // load Q tile transposed
    const float* qbase = q + ((size_t)(b * TQ + qt * 64)) * DIMC + h * HD;
    for (int f = tid; f < 1024; f += 256) {
        int r = f >> 4, d4 = (f & 15) << 2;
        float4 v = *(const float4*)(qbase + (size_t)r * DIMC + d4);
        Qst[(d4 + 0) * 65 + r] = v.x;
        Qst[(d4 + 1) * 65 + r] = v.y;
        Qst[(d4 + 2) * 65 + r] = v.z;
        Qst[(d4 + 3) * 65 + r] = v.w;
    }
    if (tid < 64) { sm_m[tid] = -1e30f; sm_l[tid] = 0.0f; }
    float o[4][4] = {};
    __syncthreads();

    for (int kt = 0; kt < NTILES; kt++) {
        const float *kp, *vp;
        float sscale;
        if (kt < 16) {
            size_t off = ((size_t)(b * TQ + kt * 64)) * DIMC + h * HD;
            kp = ktok + off; vp = vtok + off; sscale = 0.125f;
        } else if (kt < 21) {
            size_t off = ((size_t)(b * KADA + (kt - 16) * 64)) * DIMC + h * HD;
            kp = kada + off; vp = vada + off; sscale = 0.125f;
        } else {
            size_t off = ((size_t)(b * KTSK + (kt - 21) * 64)) * DIMC + h * HD;
            kp = ktsk + off; vp = vtsk + off; sscale = 0.125f * gfac;
        }

        for (int f = tid; f < 1024; f += 256) {
            int r = f >> 4, d4 = (f & 15) << 2;
            float4 kv = *(const float4*)(kp + (size_t)r * DIMC + d4);
            Kst[(d4 + 0) * 65 + r] = kv.x;
            Kst[(d4 + 1) * 65 + r] = kv.y;
            Kst[(d4 + 2) * 65 + r] = kv.z;
            Kst[(d4 + 3) * 65 + r] = kv.w;
            float4 vv = *(const float4*)(vp + (size_t)r * DIMC + d4);
            Vs[r * 65 + d4 + 0] = vv.x;
            Vs[r * 65 + d4 + 1] = vv.y;
            Vs[r * 65 + d4 + 2] = vv.z;
            Vs[r * 65 + d4 + 3] = vv.w;
        }
        __syncthreads();

        // S[key][q] = K·Q^T ; micro: rows=keys (ty), cols=q (tx)
        float sacc[4][4] = {};
#pragma unroll 8
        for (int d = 0; d < 64; d++) {
            float ka[4], qa[4];
#pragma unroll
            for (int i = 0; i < 4; i++) ka[i] = Kst[d * 65 + ty * 4 + i];
#pragma unroll
            for (int j = 0; j < 4; j++) qa[j] = Qst[d * 65 + tx * 4 + j];
#pragma unroll
            for (int i = 0; i < 4; i++)
#pragma unroll
                for (int j = 0; j < 4; j++)
                    sacc[i][j] = fmaf(ka[i], qa[j], sacc[i][j]);
        }
#pragma unroll
        for (int i = 0; i < 4; i++)
#pragma unroll
            for (int j = 0; j < 4; j++)
                Sst[(ty * 4 + i) * 65 + tx * 4 + j] = sacc[i][j] * sscale;
        __syncthreads();

        // online softmax per q column (4 threads per column)
        const int qc = tid >> 2, part = tid & 3, k0 = part * 16;
        float lm = -1e30f;
#pragma unroll
        for (int k = 0; k < 16; k++) lm = fmaxf(lm, Sst[(k0 + k) * 65 + qc]);
        red[qc * 4 + part] = lm;
        __syncthreads();
        if (part == 0) {
            float mt = fmaxf(fmaxf(red[qc * 4], red[qc * 4 + 1]),
                             fmaxf(red[qc * 4 + 2], red[qc * 4 + 3]));
            float mn = fmaxf(sm_m[qc], mt);
            sm_a[qc] = expf(sm_m[qc] - mn);
            sm_m[qc] = mn;
        }
        __syncthreads();
        const float mn = sm_m[qc];
        float lsum = 0.0f;
#pragma unroll
        for (int k = 0; k < 16; k++) {
            float pv = expf(Sst[(k0 + k) * 65 + qc] - mn);
            Sst[(k0 + k) * 65 + qc] = pv;
            lsum += pv;
        }
        red[qc * 4 + part] = lsum;
        __syncthreads();
        if (part == 0) {
            sm_l[qc] = sm_l[qc] * sm_a[qc] +
                       red[qc * 4] + red[qc * 4 + 1] + red[qc * 4 + 2] + red[qc * 4 + 3];
        }
        __syncthreads();

        // rescale O and accumulate P·V ; micro: rows=q (ty), cols=d (tx)
        float al[4];
#pragma unroll
        for (int i = 0; i < 4; i++) al[i] = sm_a[ty * 4 + i];
#pragma unroll
        for (int i = 0; i < 4; i++)
#pragma unroll
            for (int j = 0; j < 4; j++) o[i][j] *= al[i];
#pragma unroll 8
        for (int kk = 0; kk < 64; kk++) {
            float pa[4], vb[4];
#pragma unroll
            for (int i = 0; i < 4; i++) pa[i] = Sst[kk * 65 + ty * 4 + i];
#pragma unroll
            for (int j = 0; j < 4; j++) vb[j] = Vs[kk * 65 + tx * 4 + j];
#pragma unroll
            for (int i = 0; i < 4; i++)
#pragma unroll
                for (int j = 0; j < 4; j++)
                    o[i][j] = fmaf(pa[i], vb[j], o[i][j]);
        }
        __syncthreads();
    }

#pragma unroll
    for (int i = 0; i < 4; i++) {
        int qrow = ty * 4 + i;
        float inv = 1.0f / sm_l[qrow];
        float4 ov = make_float4(o[i][0] * inv, o[i][1] * inv, o[i][2] * inv, o[i][3] * inv);
        *(float4*)(out + ((size_t)(b * TQ + qt * 64 + qrow)) * DIMC + h * HD + tx * 4) = ov;
    }
}

// ---------------- LayerNorm over C=1024, one block per row ----------------
__global__ __launch_bounds__(256)
void ln_kernel(const float* __restrict__ Y, const float* __restrict__ g,
               const float* __restrict__ bb, float* __restrict__ O)
{
    const int row = blockIdx.x;
    const int tid = threadIdx.x;
    const int c = tid * 4;
    float4 v = *(const float4*)(Y + (size_t)row * DIMC + c);
    float s  = v.x + v.y + v.z + v.w;
    float sq = v.x * v.x + v.y * v.y + v.z * v.z + v.w * v.w;
#pragma unroll
    for (int off = 16; off; off >>= 1) {
        s  += __shfl_xor_sync(0xffffffffu, s, off);
        sq += __shfl_xor_sync(0xffffffffu, sq, off);
    }
    __shared__ float ws[8], wsq[8];
    __shared__ float sh_mu, sh_r;
    const int w = tid >> 5, l = tid & 31;
    if (l == 0) { ws[w] = s; wsq[w] = sq; }
    __syncthreads();
    if (tid == 0) {
        float S = 0.0f, Q = 0.0f;
#pragma unroll
        for (int i = 0; i < 8; i++) { S += ws[i]; Q += wsq[i]; }
        float mu  = S / (float)DIMC;
        float var = Q / (float)DIMC - mu * mu;
        sh_mu = mu;
        sh_r  = rsqrtf(var + 1e-5f);
    }
    __syncthreads();
    const float mu = sh_mu, r = sh_r;
    float4 gg = *(const float4*)(g + c);
    float4 b4 = *(const float4*)(bb + c);
    float4 o4;
    o4.x = (v.x - mu) * r * gg.x + b4.x;
    o4.y = (v.y - mu) * r * gg.y + b4.y;
    o4.z = (v.z - mu) * r * gg.z + b4.z;
    o4.w = (v.w - mu) * r * gg.w + b4.w;
    *(float4*)(O + (size_t)row * DIMC + c) = o4;
}

// ---------------- launcher ----------------
extern "C" void kernel_launch(void* const* d_in, const int* in_sizes, int n_in,
                              void* d_out, int out_size)
{
    const float* x    = (const float*)d_in[0];
    const float* h_t  = (const float*)d_in[1];
    const float* h_a  = (const float*)d_in[2];
    const float* p    = (const float*)d_in[3];
    const float* wq   = (const float*)d_in[4];  const float* bq  = (const float*)d_in[5];
    const float* wks  = (const float*)d_in[6];  const float* bks = (const float*)d_in[7];
    const float* wvs  = (const float*)d_in[8];  const float* bvs = (const float*)d_in[9];
    const float* wka  = (const float*)d_in[10]; const float* bka = (const float*)d_in[11];
    const float* wva  = (const float*)d_in[12]; const float* bva = (const float*)d_in[13];
    const float* wkt  = (const float*)d_in[14]; const float* bkt = (const float*)d_in[15];
    const float* wvt  = (const float*)d_in[16]; const float* bvt = (const float*)d_in[17];
    const float* wo   = (const float*)d_in[18]; const float* bo  = (const float*)d_in[19];
    const float* wf   = (const float*)d_in[20]; const float* bf  = (const float*)d_in[21];
    const float* ln_g = (const float*)d_in[22];
    const float* ln_b = (const float*)d_in[23];
    const float* gate = (const float*)d_in[24];
    float* out = (float*)d_out;

    float *q_, *ktok_, *vtok_, *had_, *kada_, *vada_, *ktsk_, *vtsk_, *attn_, *y_, *yln_;
    cudaGetSymbolAddress((void**)&q_,    g_q);
    cudaGetSymbolAddress((void**)&ktok_, g_ktok);
    cudaGetSymbolAddress((void**)&vtok_, g_vtok);
    cudaGetSymbolAddress((void**)&had_,  g_had);
    cudaGetSymbolAddress((void**)&kada_, g_kada);
    cudaGetSymbolAddress((void**)&vada_, g_vada);
    cudaGetSymbolAddress((void**)&ktsk_, g_ktsk);
    cudaGetSymbolAddress((void**)&vtsk_, g_vtsk);
    cudaGetSymbolAddress((void**)&attn_, g_attn);
    cudaGetSymbolAddress((void**)&y_,    g_y);
    cudaGetSymbolAddress((void**)&yln_,  g_yln);

    const int ATTN_SMEM = (4 * 64 * 65 + 3 * 64 + 256) * 4;   // 68352 B
    cudaFuncSetAttribute(attn_kernel, cudaFuncAttributeMaxDynamicSharedMemorySize, ATTN_SMEM);

    dim3 blk(256);

    // h_adapter = concat(h_a, p)
    concat_kernel<<<(NADROWS * DIMC / 4 + 255) / 256, 256>>>(h_a, p, had_);

    dim3 g1(16, 64);   // N/64, 4096/64
    dim3 g2(16, 20);   // 1280/64
    dim3 g3(16, 32);   // 2048/64

    sgemm_kernel<<<g1, blk>>>(x,    wq,  bq,  nullptr, q_,    NQROWS,  DIMC, DIMC, TQ,   0);
    sgemm_kernel<<<g1, blk>>>(x,    wks, bks, nullptr, ktok_, NQROWS,  DIMC, DIMC, TQ,   0);
    sgemm_kernel<<<g1, blk>>>(x,    wvs, bvs, nullptr, vtok_, NQROWS,  DIMC, DIMC, 0,    0);
    sgemm_kernel<<<g2, blk>>>(had_, wka, bka, nullptr, kada_, NADROWS, DIMC, DIMC, KADA, 0);
    sgemm_kernel<<<g2, blk>>>(had_, wva, bva, nullptr, vada_, NADROWS, DIMC, DIMC, 0,    0);
    sgemm_kernel<<<g3, blk>>>(h_t,  wkt, bkt, nullptr, ktsk_, NTKROWS, DIMC, DIMC, KTSK, 0);
    sgemm_kernel<<<g3, blk>>>(h_t,  wvt, bvt, nullptr, vtsk_, NTKROWS, DIMC, DIMC, 0,    0);

    dim3 ga(TQ / 64, HEADS, BATCH);   // (16, 16, 4)
    attn_kernel<<<ga, 256, ATTN_SMEM>>>(q_, ktok_, vtok_, kada_, vada_, ktsk_, vtsk_, gate, attn_);

    sgemm_kernel<<<g1, blk>>>(attn_, wo, bo, x, y_, NQROWS, DIMC, DIMC, 0, 0);
    ln_kernel<<<NQROWS, 256>>>(y_, ln_g, ln_b, yln_);
    sgemm_kernel<<<g1, blk>>>(yln_, wf, bf, nullptr, out, NQROWS, DIMC, DIMC, 0, 1);
}

// round 5
// speedup vs baseline: 1.0852x; 1.0852x over previous
#include <cuda_runtime.h>
#include <math.h>

#define DIMC    1024
#define BATCH   4
#define TQ      1024
#define HEADS   16
#define HD      64
#define KADA    320
#define KTSK    512
#define NQROWS  (BATCH*TQ)     /* 4096 */
#define NADROWS (BATCH*KADA)   /* 1280 */
#define NTKROWS (BATCH*KTSK)   /* 2048 */
#define NTILES  29             /* 16 tok + 5 ada + 8 tsk, 64 keys each = 1856 */

// ---------------- scratch (device globals; no runtime allocation) ----------------
__device__ float g_q   [NQROWS * DIMC];
__device__ float g_ktok[NQROWS * DIMC];
__device__ float g_vtok[NQROWS * DIMC];
__device__ float g_had [NADROWS * DIMC];
__device__ float g_kada[NADROWS * DIMC];
__device__ float g_vada[NADROWS * DIMC];
__device__ float g_ktsk[NTKROWS * DIMC];
__device__ float g_vtsk[NTKROWS * DIMC];
__device__ float g_attn[NQROWS * DIMC];
__device__ float g_y   [NQROWS * DIMC];
__device__ float g_yln [NQROWS * DIMC];

// ---------------- h_adapter = concat(h_a, p) along seq ----------------
__global__ void concat_kernel(const float* __restrict__ ha,
                              const float* __restrict__ pp,
                              float* __restrict__ out)
{
    int idx = blockIdx.x * blockDim.x + threadIdx.x;     // float4 index
    const int C4 = DIMC / 4;
    const int total = NADROWS * C4;
    if (idx >= total) return;
    int c4  = idx % C4;
    int row = idx / C4;
    int b = row / KADA;
    int s = row % KADA;
    float4 v;
    if (s < 256) v = ((const float4*)ha)[(size_t)(b * 256 + s) * C4 + c4];
    else         v = ((const float4*)pp)[(size_t)(b * 64 + (s - 256)) * C4 + c4];
    ((float4*)out)[idx] = v;
}

// ---------------- SGEMM: C = A[MxK] @ W[KxN] + bias (+res) (rope/relu epilogue) --
// 128x128 block tile, BK=8, 256 threads, 8x8 micro-tile, register prefetch.
__global__ __launch_bounds__(256, 2)
void sgemm_kernel(const float* __restrict__ A, const float* __restrict__ W,
                  const float* __restrict__ bias, const float* __restrict__ res,
                  float* __restrict__ C, int M, int K, int N,
                  int rope_seq, int do_relu)
{
    __shared__ float As[8][132];   // transposed: As[k][m]
    __shared__ float Bs[8][128];   // Bs[k][n]

    const int tid = threadIdx.x;
    const int tx = tid & 15, ty = tid >> 4;
    const int bm = blockIdx.y * 128, bn = blockIdx.x * 128;
    const int aRow = tid >> 1,  aK   = (tid & 1) << 2;   // 128 rows x 8 cols
    const int bRow = tid >> 5,  bCol = (tid & 31) << 2;  // 8 rows x 128 cols
    const float* Aptr = A + (size_t)(bm + aRow) * K + aK;
    const float* Wptr = W + (size_t)bRow * N + bn + bCol;

    float acc[8][8] = {};
    float4 a_n = *(const float4*)(Aptr);
    float4 b_n = *(const float4*)(Wptr);

    for (int k0 = 0; k0 < K; k0 += 8) {
        As[aK + 0][aRow] = a_n.x;
        As[aK + 1][aRow] = a_n.y;
        As[aK + 2][aRow] = a_n.z;
        As[aK + 3][aRow] = a_n.w;
        *(float4*)&Bs[bRow][bCol] = b_n;
        __syncthreads();
        if (k0 + 8 < K) {
            a_n = *(const float4*)(Aptr + k0 + 8);
            b_n = *(const float4*)(Wptr + (size_t)(k0 + 8) * N);
        }
#pragma unroll
        for (int k = 0; k < 8; k++) {
            float a[8], b[8];
            *(float4*)(a)     = *(const float4*)&As[k][ty * 4];
            *(float4*)(a + 4) = *(const float4*)&As[k][64 + ty * 4];
            *(float4*)(b)     = *(const float4*)&Bs[k][tx * 4];
            *(float4*)(b + 4) = *(const float4*)&Bs[k][64 + tx * 4];
#pragma unroll
            for (int i = 0; i < 8; i++)
#pragma unroll
                for (int j = 0; j < 8; j++)
                    acc[i][j] = fmaf(a[i], b[j], acc[i][j]);
        }
        __syncthreads();
    }

    // epilogue: rows r(i) = bm + (i>>2)*64 + ty*4 + (i&3); col halves jh*64 + tx*4
#pragma unroll
    for (int i = 0; i < 8; i++) {
        const int gRow = bm + (i >> 2) * 64 + ty * 4 + (i & 3);
#pragma unroll
        for (int jh = 0; jh < 2; jh++) {
            const int gCol0 = bn + jh * 64 + tx * 4;
            float v[4];
#pragma unroll
            for (int j = 0; j < 4; j++) v[j] = acc[i][jh * 4 + j] + bias[gCol0 + j];
            if (res) {
                const float* rr = res + (size_t)gRow * N + gCol0;
#pragma unroll
                for (int j = 0; j < 4; j++) v[j] += rr[j];
            }
            if (rope_seq) {
                const int pos = gRow % rope_seq;
                const float fp = (float)pos;
#pragma unroll
                for (int j = 0; j < 4; j += 2) {
                    int d  = (gCol0 + j) & 63;
                    int f0 = d & 31;                  // concat tables: freq idx = d % 32
                    float inv0 = exp2f((float)f0       * -0.41524101186409203f);
                    float inv1 = exp2f((float)(f0 + 1) * -0.41524101186409203f);
                    float s0, c0, s1, c1;
                    sincosf(fp * inv0, &s0, &c0);
                    sincosf(fp * inv1, &s1, &c1);
                    float e = v[j], o = v[j + 1];
                    v[j]     = e * c0 - o * s0;
                    v[j + 1] = o * c1 + e * s1;
                }
            }
            if (do_relu) {
#pragma unroll
                for (int j = 0; j < 4; j++) v[j] = fmaxf(v[j], 0.0f);
            }
            float4 o4 = make_float4(v[0], v[1], v[2], v[3]);
            *(float4*)(C + (size_t)gRow * N + gCol0) = o4;
        }
    }
}

// ---------------- flash attention over 3 concatenated KV sources ----------------
// Block = (qtile, head, batch); 128 q rows, 64-key tiles, online softmax.
__global__ __launch_bounds__(256, 2)
void attn_kernel(const float* __restrict__ q,
                 const float* __restrict__ ktok, const float* __restrict__ vtok,
                 const float* __restrict__ kada, const float* __restrict__ vada,
                 const float* __restrict__ ktsk, const float* __restrict__ vtsk,
                 const float* __restrict__ gate, float* __restrict__ out)
{
    extern __shared__ float sm[];
    float* Qs   = sm;                 // [d][q]   64x132
    float* Ks   = Qs + 64 * 132;      // [d][key] 64x68
    float* Vs   = Ks + 64 * 68;       // [key][d] 64x68
    float* Ss   = Vs + 64 * 68;       // [key][q] 64x132
    float* sm_m = Ss + 64 * 132;      // 128
    float* sm_l = sm_m + 128;         // 128
    float* sm_a = sm_l + 128;         // 128
    float* red  = sm_a + 128;         // 256

    const int b = blockIdx.z, h = blockIdx.y, qt = blockIdx.x;
    const int tid = threadIdx.x;
    const int tx = tid & 15, ty = tid >> 4;
    const float gfac = tanhf(gate[0]);

    // load Q tile (128 rows x 64 d) transposed; lane-major in rows -> conflict-free
    const float* qbase = q + ((size_t)(b * TQ + qt * 128)) * DIMC + h * HD;
    for (int f = tid; f < 2048; f += 256) {
        int r = f & 127, d4 = (f >> 7) << 2;
        float4 v = *(const float4*)(qbase + (size_t)r * DIMC + d4);
        Qs[(d4 + 0) * 132 + r] = v.x;
        Qs[(d4 + 1) * 132 + r] = v.y;
        Qs[(d4 + 2) * 132 + r] = v.z;
        Qs[(d4 + 3) * 132 + r] = v.w;
    }
    if (tid < 128) { sm_m[tid] = -1e30f; sm_l[tid] = 0.0f; }
    float o[8][4] = {};
    __syncthreads();

    for (int kt = 0; kt < NTILES; kt++) {
        const float *kp, *vp;
        float sscale;
        if (kt < 16) {
            size_t off = ((size_t)(b * TQ + kt * 64)) * DIMC + h * HD;
            kp = ktok + off; vp = vtok + off; sscale = 0.125f;
        } else if (kt < 21) {
            size_t off = ((size_t)(b * KADA + (kt - 16) * 64)) * DIMC + h * HD;
            kp = kada + off; vp = vada + off; sscale = 0.125f;
        } else {
            size_t off = ((size_t)(b * KTSK + (kt - 21) * 64)) * DIMC + h * HD;
            kp = ktsk + off; vp = vtsk + off; sscale = 0.125f * gfac;
        }

        // K transposed (lane-major rows), V row-major
        for (int f = tid; f < 1024; f += 256) {
            int rK = f & 63, dK = (f >> 6) << 2;
            float4 kv = *(const float4*)(kp + (size_t)rK * DIMC + dK);
            Ks[(dK + 0) * 68 + rK] = kv.x;
            Ks[(dK + 1) * 68 + rK] = kv.y;
            Ks[(dK + 2) * 68 + rK] = kv.z;
            Ks[(dK + 3) * 68 + rK] = kv.w;
            int rV = f >> 4, dV = (f & 15) << 2;
            float4 vv = *(const float4*)(vp + (size_t)rV * DIMC + dV);
            *(float4*)&Vs[rV * 68 + dV] = vv;
        }
        __syncthreads();

        // S[key][q] = K·Q^T ; micro: 4 keys (ty) x 8 q (tx)
        float sacc[4][8] = {};
#pragma unroll 8
        for (int d = 0; d < 64; d++) {
            float ka[4], qa[8];
            *(float4*)(ka)     = *(const float4*)&Ks[d * 68 + ty * 4];
            *(float4*)(qa)     = *(const float4*)&Qs[d * 132 + tx * 8];
            *(float4*)(qa + 4) = *(const float4*)&Qs[d * 132 + tx * 8 + 4];
#pragma unroll
            for (int i = 0; i < 4; i++)
#pragma unroll
                for (int j = 0; j < 8; j++)
                    sacc[i][j] = fmaf(ka[i], qa[j], sacc[i][j]);
        }
#pragma unroll
        for (int i = 0; i < 4; i++) {
            float* sp = &Ss[(ty * 4 + i) * 132 + tx * 8];
            float4 s0 = make_float4(sacc[i][0] * sscale, sacc[i][1] * sscale,
                                    sacc[i][2] * sscale, sacc[i][3] * sscale);
            float4 s1 = make_float4(sacc[i][4] * sscale, sacc[i][5] * sscale,
                                    sacc[i][6] * sscale, sacc[i][7] * sscale);
            *(float4*)(sp)     = s0;
            *(float4*)(sp + 4) = s1;
        }
        __syncthreads();

        // online softmax per q column (2 threads per column, 32 keys each)
        const int qc = tid >> 1, part = tid & 1, k0 = part * 32;
        float lm = -1e30f;
#pragma unroll
        for (int k = 0; k < 32; k++) lm = fmaxf(lm, Ss[(k0 + k) * 132 + qc]);
        red[qc * 2 + part] = lm;
        __syncthreads();
        if (part == 0) {
            float mt = fmaxf(red[qc * 2], red[qc * 2 + 1]);
            float mn = fmaxf(sm_m[qc], mt);
            sm_a[qc] = __expf(sm_m[qc] - mn);
            sm_m[qc] = mn;
        }
        __syncthreads();
        const float mn = sm_m[qc];
        float lsum = 0.0f;
#pragma unroll
        for (int k = 0; k < 32; k++) {
            float pv = __expf(Ss[(k0 + k) * 132 + qc] - mn);
            Ss[(k0 + k) * 132 + qc] = pv;
            lsum += pv;
        }
        red[qc * 2 + part] = lsum;
        __syncthreads();
        if (part == 0)
            sm_l[qc] = sm_l[qc] * sm_a[qc] + red[qc * 2] + red[qc * 2 + 1];
        __syncthreads();

        // rescale O, accumulate P·V ; micro: 8 q (ty) x 4 d (tx)
        float al[8];
#pragma unroll
        for (int i = 0; i < 8; i++) al[i] = sm_a[ty * 8 + i];
#pragma unroll
        for (int i = 0; i < 8; i++)
#pragma unroll
            for (int j = 0; j < 4; j++) o[i][j] *= al[i];
#pragma unroll 8
        for (int kk = 0; kk < 64; kk++) {
            float pa[8], vb[4];
            *(float4*)(pa)     = *(const float4*)&Ss[kk * 132 + ty * 8];
            *(float4*)(pa + 4) = *(const float4*)&Ss[kk * 132 + ty * 8 + 4];
            *(float4*)(vb)     = *(const float4*)&Vs[kk * 68 + tx * 4];
#pragma unroll
            for (int i = 0; i < 8; i++)
#pragma unroll
                for (int j = 0; j < 4; j++)
                    o[i][j] = fmaf(pa[i], vb[j], o[i][j]);
        }
        __syncthreads();
    }

#pragma unroll
    for (int i = 0; i < 8; i++) {
        int qrow = ty * 8 + i;
        float inv = 1.0f / sm_l[qrow];
        float4 ov = make_float4(o[i][0] * inv, o[i][1] * inv, o[i][2] * inv, o[i][3] * inv);
        *(float4*)(out + ((size_t)(b * TQ + qt * 128 + qrow)) * DIMC + h * HD + tx * 4) = ov;
    }
}

// ---------------- LayerNorm over C=1024, one block per row ----------------
__global__ __launch_bounds__(256)
void ln_kernel(const float* __restrict__ Y, const float* __restrict__ g,
               const float* __restrict__ bb, float* __restrict__ O)
{
    const int row = blockIdx.x;
    const int tid = threadIdx.x;
    const int c = tid * 4;
    float4 v = *(const float4*)(Y + (size_t)row * DIMC + c);
    float s  = v.x + v.y + v.z + v.w;
    float sq = v.x * v.x + v.y * v.y + v.z * v.z + v.w * v.w;
#pragma unroll
    for (int off = 16; off; off >>= 1) {
        s  += __shfl_xor_sync(0xffffffffu, s, off);
        sq += __shfl_xor_sync(0xffffffffu, sq, off);
    }
    __shared__ float ws[8], wsq[8];
    __shared__ float sh_mu, sh_r;
    const int w = tid >> 5, l = tid & 31;
    if (l == 0) { ws[w] = s; wsq[w] = sq; }
    __syncthreads();
    if (tid == 0) {
        float S = 0.0f, Q = 0.0f;
#pragma unroll
        for (int i = 0; i < 8; i++) { S += ws[i]; Q += wsq[i]; }
        float mu  = S / (float)DIMC;
        float var = Q / (float)DIMC - mu * mu;
        sh_mu = mu;
        sh_r  = rsqrtf(var + 1e-5f);
    }
    __syncthreads();
    const float mu = sh_mu, r = sh_r;
    float4 gg = *(const float4*)(g + c);
    float4 b4 = *(const float4*)(bb + c);
    float4 o4;
    o4.x = (v.x - mu) * r * gg.x + b4.x;
    o4.y = (v.y - mu) * r * gg.y + b4.y;
    o4.z = (v.z - mu) * r * gg.z + b4.z;
    o4.w = (v.w - mu) * r * gg.w + b4.w;
    *(float4*)(O + (size_t)row * DIMC + c) = o4;
}

// ---------------- launcher ----------------
extern "C" void kernel_launch(void* const* d_in, const int* in_sizes, int n_in,
                              void* d_out, int out_size)
{
    const float* x    = (const float*)d_in[0];
    const float* h_t  = (const float*)d_in[1];
    const float* h_a  = (const float*)d_in[2];
    const float* p    = (const float*)d_in[3];
    const float* wq   = (const float*)d_in[4];  const float* bq  = (const float*)d_in[5];
    const float* wks  = (const float*)d_in[6];  const float* bks = (const float*)d_in[7];
    const float* wvs  = (const float*)d_in[8];  const float* bvs = (const float*)d_in[9];
    const float* wka  = (const float*)d_in[10]; const float* bka = (const float*)d_in[11];
    const float* wva  = (const float*)d_in[12]; const float* bva = (const float*)d_in[13];
    const float* wkt  = (const float*)d_in[14]; const float* bkt = (const float*)d_in[15];
    const float* wvt  = (const float*)d_in[16]; const float* bvt = (const float*)d_in[17];
    const float* wo   = (const float*)d_in[18]; const float* bo  = (const float*)d_in[19];
    const float* wf   = (const float*)d_in[20]; const float* bf  = (const float*)d_in[21];
    const float* ln_g = (const float*)d_in[22];
    const float* ln_b = (const float*)d_in[23];
    const float* gate = (const float*)d_in[24];
    float* out = (float*)d_out;

    float *q_, *ktok_, *vtok_, *had_, *kada_, *vada_, *ktsk_, *vtsk_, *attn_, *y_, *yln_;
    cudaGetSymbolAddress((void**)&q_,    g_q);
    cudaGetSymbolAddress((void**)&ktok_, g_ktok);
    cudaGetSymbolAddress((void**)&vtok_, g_vtok);
    cudaGetSymbolAddress((void**)&had_,  g_had);
    cudaGetSymbolAddress((void**)&kada_, g_kada);
    cudaGetSymbolAddress((void**)&vada_, g_vada);
    cudaGetSymbolAddress((void**)&ktsk_, g_ktsk);
    cudaGetSymbolAddress((void**)&vtsk_, g_vtsk);
    cudaGetSymbolAddress((void**)&attn_, g_attn);
    cudaGetSymbolAddress((void**)&y_,    g_y);
    cudaGetSymbolAddress((void**)&yln_,  g_yln);

    const int ATTN_SMEM = (64 * 132 + 64 * 68 + 64 * 68 + 64 * 132 + 3 * 128 + 256) * 4; // 104960 B
    cudaFuncSetAttribute(attn_kernel, cudaFuncAttributeMaxDynamicSharedMemorySize, ATTN_SMEM);

    dim3 blk(256);

    // h_adapter = concat(h_a, p)
    concat_kernel<<<(NADROWS * DIMC / 4 + 255) / 256, 256>>>(h_a, p, had_);

    dim3 g1(8, 32);    // N/128, 4096/128
    dim3 g2(8, 10);    // 1280/128
    dim3 g3(8, 16);    // 2048/128

    sgemm_kernel<<<g1, blk>>>(x,    wq,  bq,  nullptr, q_,    NQROWS,  DIMC, DIMC, TQ,   0);
    sgemm_kernel<<<g1, blk>>>(x,    wks, bks, nullptr, ktok_, NQROWS,  DIMC, DIMC, TQ,   0);
    sgemm_kernel<<<g1, blk>>>(x,    wvs, bvs, nullptr, vtok_, NQROWS,  DIMC, DIMC, 0,    0);
    sgemm_kernel<<<g2, blk>>>(had_, wka, bka, nullptr, kada_, NADROWS, DIMC, DIMC, KADA, 0);
    sgemm_kernel<<<g2, blk>>>(had_, wva, bva, nullptr, vada_, NADROWS, DIMC, DIMC, 0,    0);
    sgemm_kernel<<<g3, blk>>>(h_t,  wkt, bkt, nullptr, ktsk_, NTKROWS, DIMC, DIMC, KTSK, 0);
    sgemm_kernel<<<g3, blk>>>(h_t,  wvt, bvt, nullptr, vtsk_, NTKROWS, DIMC, DIMC, 0,    0);

    dim3 ga(TQ / 128, HEADS, BATCH);   // (8, 16, 4)
    attn_kernel<<<ga, 256, ATTN_SMEM>>>(q_, ktok_, vtok_, kada_, vada_, ktsk_, vtsk_, gate, attn_);

    sgemm_kernel<<<g1, blk>>>(attn_, wo, bo, x, y_, NQROWS, DIMC, DIMC, 0, 0);
    ln_kernel<<<NQROWS, 256>>>(y_, ln_g, ln_b, yln_);
    sgemm_kernel<<<g1, blk>>>(yln_, wf, bf, nullptr, out, NQROWS, DIMC, DIMC, 0, 1);
}

// round 10
// speedup vs baseline: 1.5571x; 1.4348x over previous
#include <cuda_runtime.h>
#include <math.h>
#include <stdint.h>

#define DIMC    1024
#define BATCH   4
#define TQ      1024
#define HEADS   16
#define HD      64
#define KADA    320
#define KTSK    512
#define NQROWS  (BATCH*TQ)     /* 4096 */
#define NADROWS (BATCH*KADA)   /* 1280 */
#define NTKROWS (BATCH*KTSK)   /* 2048 */
#define NTILES  29             /* 16 tok + 5 ada + 8 tsk, 64 keys each = 1856 */

// ---------------- scratch (device globals; no runtime allocation) ----------------
__device__ float g_q   [NQROWS * DIMC];
__device__ float g_ktok[NQROWS * DIMC];
__device__ float g_vtok[NQROWS * DIMC];
__device__ float g_had [NADROWS * DIMC];
__device__ float g_kada[NADROWS * DIMC];
__device__ float g_vada[NADROWS * DIMC];
__device__ float g_ktsk[NTKROWS * DIMC];
__device__ float g_vtsk[NTKROWS * DIMC];
__device__ float g_attn[NQROWS * DIMC];
__device__ float g_y   [NQROWS * DIMC];
__device__ float g_yln [NQROWS * DIMC];

// ---------------- h_adapter = concat(h_a, p) along seq ----------------
__global__ void concat_kernel(const float* __restrict__ ha,
                              const float* __restrict__ pp,
                              float* __restrict__ out)
{
    int idx = blockIdx.x * blockDim.x + threadIdx.x;     // float4 index
    const int C4 = DIMC / 4;
    const int total = NADROWS * C4;
    if (idx >= total) return;
    int c4  = idx % C4;
    int row = idx / C4;
    int b = row / KADA;
    int s = row % KADA;
    float4 v;
    if (s < 256) v = ((const float4*)ha)[(size_t)(b * 256 + s) * C4 + c4];
    else         v = ((const float4*)pp)[(size_t)(b * 64 + (s - 256)) * C4 + c4];
    ((float4*)out)[idx] = v;
}

// ---------------- tf32 helpers ----------------
__device__ __forceinline__ float tf32r(float x) {
    uint32_t u;
    asm("cvt.rna.tf32.f32 %0, %1;" : "=r"(u) : "f"(x));
    return __uint_as_float(u);
}
__device__ __forceinline__ float4 tf32r4(float4 v) {
    return make_float4(tf32r(v.x), tf32r(v.y), tf32r(v.z), tf32r(v.w));
}

// ---------------- TF32 tensor-core GEMM ----------------
// C[MxN] = A[MxK] @ W[KxN] + bias (+res) (+rope/relu epilogue)
// 128x128 CTA tile, BK=16, 256 threads = 8 warps in 2(m) x 4(n) grid,
// warp tile 64x32 via mma.sync.m16n8k8.tf32. Conflict-free smem (pitch 136).
#define SPITCH 136
__global__ __launch_bounds__(256, 2)
void gemm_tf32_kernel(const float* __restrict__ A, const float* __restrict__ W,
                      const float* __restrict__ bias, const float* __restrict__ res,
                      float* __restrict__ C, int M, int K, int N,
                      int rope_seq, int do_relu)
{
    __shared__ float As[16][SPITCH];   // As[k][m]  (transposed)
    __shared__ float Bs[16][SPITCH];   // Bs[k][n]

    const int tid  = threadIdx.x;
    const int lane = tid & 31, warp = tid >> 5;
    const int grp  = lane >> 2, tig = lane & 3;
    const int wm   = (warp >> 2) * 64;    // 0 / 64
    const int wn   = (warp & 3) * 32;     // 0,32,64,96
    const int bm = blockIdx.y * 128, bn = blockIdx.x * 128;

    const int aRow = tid >> 2,  aK   = (tid & 3) << 2;   // 64 rows (+64), 4-wide k
    const int bRow = tid >> 5,  bCol = (tid & 31) << 2;  // 8 k-rows (+8), 4-wide n
    const float* Aptr = A + (size_t)(bm + aRow) * K + aK;
    const float* Wptr = W + (size_t)bRow * N + bn + bCol;

    float acc[4][4][4];
#pragma unroll
    for (int i = 0; i < 4; i++)
#pragma unroll
        for (int j = 0; j < 4; j++)
#pragma unroll
            for (int r = 0; r < 4; r++) acc[i][j][r] = 0.0f;

    float4 a0n = *(const float4*)(Aptr);
    float4 a1n = *(const float4*)(Aptr + (size_t)64 * K);
    float4 b0n = *(const float4*)(Wptr);
    float4 b1n = *(const float4*)(Wptr + (size_t)8 * N);

    for (int k0 = 0; k0 < K; k0 += 16) {
        float4 a0 = tf32r4(a0n), a1 = tf32r4(a1n);
        float4 b0 = tf32r4(b0n), b1 = tf32r4(b1n);
        As[aK + 0][aRow]      = a0.x;
        As[aK + 1][aRow]      = a0.y;
        As[aK + 2][aRow]      = a0.z;
        As[aK + 3][aRow]      = a0.w;
        As[aK + 0][aRow + 64] = a1.x;
        As[aK + 1][aRow + 64] = a1.y;
        As[aK + 2][aRow + 64] = a1.z;
        As[aK + 3][aRow + 64] = a1.w;
        *(float4*)&Bs[bRow][bCol]     = b0;
        *(float4*)&Bs[bRow + 8][bCol] = b1;
        __syncthreads();

        if (k0 + 16 < K) {
            a0n = *(const float4*)(Aptr + k0 + 16);
            a1n = *(const float4*)(Aptr + (size_t)64 * K + k0 + 16);
            b0n = *(const float4*)(Wptr + (size_t)(k0 + 16) * N);
            b1n = *(const float4*)(Wptr + (size_t)(k0 + 24) * N);
        }

#pragma unroll
        for (int kk = 0; kk < 16; kk += 8) {
            uint32_t af[4][4], bf[4][2];
#pragma unroll
            for (int mi = 0; mi < 4; mi++) {
                const int m0 = wm + mi * 16 + grp;
                af[mi][0] = __float_as_uint(As[kk + tig][m0]);
                af[mi][1] = __float_as_uint(As[kk + tig][m0 + 8]);
                af[mi][2] = __float_as_uint(As[kk + tig + 4][m0]);
                af[mi][3] = __float_as_uint(As[kk + tig + 4][m0 + 8]);
            }
#pragma unroll
            for (int ni = 0; ni < 4; ni++) {
                const int n0 = wn + ni * 8 + grp;
                bf[ni][0] = __float_as_uint(Bs[kk + tig][n0]);
                bf[ni][1] = __float_as_uint(Bs[kk + tig + 4][n0]);
            }
#pragma unroll
            for (int mi = 0; mi < 4; mi++)
#pragma unroll
                for (int ni = 0; ni < 4; ni++) {
                    asm volatile(
                        "mma.sync.aligned.m16n8k8.row.col.f32.tf32.tf32.f32 "
                        "{%0,%1,%2,%3}, {%4,%5,%6,%7}, {%8,%9}, {%0,%1,%2,%3};\n"
                        : "+f"(acc[mi][ni][0]), "+f"(acc[mi][ni][1]),
                          "+f"(acc[mi][ni][2]), "+f"(acc[mi][ni][3])
                        : "r"(af[mi][0]), "r"(af[mi][1]), "r"(af[mi][2]), "r"(af[mi][3]),
                          "r"(bf[ni][0]), "r"(bf[ni][1]));
                }
        }
        __syncthreads();
    }

    // epilogue: each thread owns pairs (col, col+1) with col even -> rope pairs align.
#pragma unroll
    for (int mi = 0; mi < 4; mi++) {
#pragma unroll
        for (int half = 0; half < 2; half++) {
            const int gRow = bm + wm + mi * 16 + grp + half * 8;
            const int pos = rope_seq ? (gRow % rope_seq) : 0;
            const float fp = (float)pos;
#pragma unroll
            for (int ni = 0; ni < 4; ni++) {
                const int gCol = bn + wn + ni * 8 + tig * 2;
                float v0 = acc[mi][ni][half * 2 + 0] + bias[gCol];
                float v1 = acc[mi][ni][half * 2 + 1] + bias[gCol + 1];
                if (res) {
                    const float* rr = res + (size_t)gRow * N + gCol;
                    v0 += rr[0];
                    v1 += rr[1];
                }
                if (rope_seq) {
                    const int d  = gCol & 63;       // even
                    const int f0 = d & 31;          // concat tables: freq idx = d % 32
                    float inv0 = exp2f((float)f0       * -0.41524101186409203f);
                    float inv1 = exp2f((float)(f0 + 1) * -0.41524101186409203f);
                    float s0, c0, s1, c1;
                    sincosf(fp * inv0, &s0, &c0);
                    sincosf(fp * inv1, &s1, &c1);
                    float e = v0, o = v1;
                    v0 = e * c0 - o * s0;
                    v1 = o * c1 + e * s1;
                }
                if (do_relu) {
                    v0 = fmaxf(v0, 0.0f);
                    v1 = fmaxf(v1, 0.0f);
                }
                *(float2*)(C + (size_t)gRow * N + gCol) = make_float2(v0, v1);
            }
        }
    }
}

// ---------------- flash attention over 3 concatenated KV sources ----------------
// Block = (qtile, head, batch); 128 q rows, 64-key tiles, online softmax.
__global__ __launch_bounds__(256, 2)
void attn_kernel(const float* __restrict__ q,
                 const float* __restrict__ ktok, const float* __restrict__ vtok,
                 const float* __restrict__ kada, const float* __restrict__ vada,
                 const float* __restrict__ ktsk, const float* __restrict__ vtsk,
                 const float* __restrict__ gate, float* __restrict__ out)
{
    extern __shared__ float sm[];
    float* Qs   = sm;                 // [d][q]   64x132
    float* Ks   = Qs + 64 * 132;      // [d][key] 64x68
    float* Vs   = Ks + 64 * 68;       // [key][d] 64x68
    float* Ss   = Vs + 64 * 68;       // [key][q] 64x132
    float* sm_m = Ss + 64 * 132;      // 128
    float* sm_l = sm_m + 128;         // 128
    float* sm_a = sm_l + 128;         // 128
    float* red  = sm_a + 128;         // 256

    const int b = blockIdx.z, h = blockIdx.y, qt = blockIdx.x;
    const int tid = threadIdx.x;
    const int tx = tid & 15, ty = tid >> 4;
    const float gfac = tanhf(gate[0]);

    // load Q tile (128 rows x 64 d) transposed; lane-major in rows -> conflict-free
    const float* qbase = q + ((size_t)(b * TQ + qt * 128)) * DIMC + h * HD;
    for (int f = tid; f < 2048; f += 256) {
        int r = f & 127, d4 = (f >> 7) << 2;
        float4 v = *(const float4*)(qbase + (size_t)r * DIMC + d4);
        Qs[(d4 + 0) * 132 + r] = v.x;
        Qs[(d4 + 1) * 132 + r] = v.y;
        Qs[(d4 + 2) * 132 + r] = v.z;
        Qs[(d4 + 3) * 132 + r] = v.w;
    }
    if (tid < 128) { sm_m[tid] = -1e30f; sm_l[tid] = 0.0f; }
    float o[8][4] = {};
    __syncthreads();

    for (int kt = 0; kt < NTILES; kt++) {
        const float *kp, *vp;
        float sscale;
        if (kt < 16) {
            size_t off = ((size_t)(b * TQ + kt * 64)) * DIMC + h * HD;
            kp = ktok + off; vp = vtok + off; sscale = 0.125f;
        } else if (kt < 21) {
            size_t off = ((size_t)(b * KADA + (kt - 16) * 64)) * DIMC + h * HD;
            kp = kada + off; vp = vada + off; sscale = 0.125f;
        } else {
            size_t off = ((size_t)(b * KTSK + (kt - 21) * 64)) * DIMC + h * HD;
            kp = ktsk + off; vp = vtsk + off; sscale = 0.125f * gfac;
        }

        // K transposed (lane-major rows), V row-major
        for (int f = tid; f < 1024; f += 256) {
            int rK = f & 63, dK = (f >> 6) << 2;
            float4 kv = *(const float4*)(kp + (size_t)rK * DIMC + dK);
            Ks[(dK + 0) * 68 + rK] = kv.x;
            Ks[(dK + 1) * 68 + rK] = kv.y;
            Ks[(dK + 2) * 68 + rK] = kv.z;
            Ks[(dK + 3) * 68 + rK] = kv.w;
            int rV = f >> 4, dV = (f & 15) << 2;
            float4 vv = *(const float4*)(vp + (size_t)rV * DIMC + dV);
            *(float4*)&Vs[rV * 68 + dV] = vv;
        }
        __syncthreads();

        // S[key][q] = K·Q^T ; micro: 4 keys (ty) x 8 q (tx)
        float sacc[4][8] = {};
#pragma unroll 8
        for (int d = 0; d < 64; d++) {
            float ka[4], qa[8];
            *(float4*)(ka)     = *(const float4*)&Ks[d * 68 + ty * 4];
            *(float4*)(qa)     = *(const float4*)&Qs[d * 132 + tx * 8];
            *(float4*)(qa + 4) = *(const float4*)&Qs[d * 132 + tx * 8 + 4];
#pragma unroll
            for (int i = 0; i < 4; i++)
#pragma unroll
                for (int j = 0; j < 8; j++)
                    sacc[i][j] = fmaf(ka[i], qa[j], sacc[i][j]);
        }
#pragma unroll
        for (int i = 0; i < 4; i++) {
            float* sp = &Ss[(ty * 4 + i) * 132 + tx * 8];
            float4 s0 = make_float4(sacc[i][0] * sscale, sacc[i][1] * sscale,
                                    sacc[i][2] * sscale, sacc[i][3] * sscale);
            float4 s1 = make_float4(sacc[i][4] * sscale, sacc[i][5] * sscale,
                                    sacc[i][6] * sscale, sacc[i][7] * sscale);
            *(float4*)(sp)     = s0;
            *(float4*)(sp + 4) = s1;
        }
        __syncthreads();

        // online softmax per q column (2 threads per column, 32 keys each)
        const int qc = tid >> 1, part = tid & 1, k0 = part * 32;
        float lm = -1e30f;
#pragma unroll
        for (int k = 0; k < 32; k++) lm = fmaxf(lm, Ss[(k0 + k) * 132 + qc]);
        red[qc * 2 + part] = lm;
        __syncthreads();
        if (part == 0) {
            float mt = fmaxf(red[qc * 2], red[qc * 2 + 1]);
            float mn = fmaxf(sm_m[qc], mt);
            sm_a[qc] = __expf(sm_m[qc] - mn);
            sm_m[qc] = mn;
        }
        __syncthreads();
        const float mn = sm_m[qc];
        float lsum = 0.0f;
#pragma unroll
        for (int k = 0; k < 32; k++) {
            float pv = __expf(Ss[(k0 + k) * 132 + qc] - mn);
            Ss[(k0 + k) * 132 + qc] = pv;
            lsum += pv;
        }
        red[qc * 2 + part] = lsum;
        __syncthreads();
        if (part == 0)
            sm_l[qc] = sm_l[qc] * sm_a[qc] + red[qc * 2] + red[qc * 2 + 1];
        __syncthreads();

        // rescale O, accumulate P·V ; micro: 8 q (ty) x 4 d (tx)
        float al[8];
#pragma unroll
        for (int i = 0; i < 8; i++) al[i] = sm_a[ty * 8 + i];
#pragma unroll
        for (int i = 0; i < 8; i++)
#pragma unroll
            for (int j = 0; j < 4; j++) o[i][j] *= al[i];
#pragma unroll 8
        for (int kk = 0; kk < 64; kk++) {
            float pa[8], vb[4];
            *(float4*)(pa)     = *(const float4*)&Ss[kk * 132 + ty * 8];
            *(float4*)(pa + 4) = *(const float4*)&Ss[kk * 132 + ty * 8 + 4];
            *(float4*)(vb)     = *(const float4*)&Vs[kk * 68 + tx * 4];
#pragma unroll
            for (int i = 0; i < 8; i++)
#pragma unroll
                for (int j = 0; j < 4; j++)
                    o[i][j] = fmaf(pa[i], vb[j], o[i][j]);
        }
        __syncthreads();
    }

#pragma unroll
    for (int i = 0; i < 8; i++) {
        int qrow = ty * 8 + i;
        float inv = 1.0f / sm_l[qrow];
        float4 ov = make_float4(o[i][0] * inv, o[i][1] * inv, o[i][2] * inv, o[i][3] * inv);
        *(float4*)(out + ((size_t)(b * TQ + qt * 128 + qrow)) * DIMC + h * HD + tx * 4) = ov;
    }
}

// ---------------- LayerNorm over C=1024, one block per row ----------------
__global__ __launch_bounds__(256)
void ln_kernel(const float* __restrict__ Y, const float* __restrict__ g,
               const float* __restrict__ bb, float* __restrict__ O)
{
    const int row = blockIdx.x;
    const int tid = threadIdx.x;
    const int c = tid * 4;
    float4 v = *(const float4*)(Y + (size_t)row * DIMC + c);
    float s  = v.x + v.y + v.z + v.w;
    float sq = v.x * v.x + v.y * v.y + v.z * v.z + v.w * v.w;
#pragma unroll
    for (int off = 16; off; off >>= 1) {
        s  += __shfl_xor_sync(0xffffffffu, s, off);
        sq += __shfl_xor_sync(0xffffffffu, sq, off);
    }
    __shared__ float ws[8], wsq[8];
    __shared__ float sh_mu, sh_r;
    const int w = tid >> 5, l = tid & 31;
    if (l == 0) { ws[w] = s; wsq[w] = sq; }
    __syncthreads();
    if (tid == 0) {
        float S = 0.0f, Q = 0.0f;
#pragma unroll
        for (int i = 0; i < 8; i++) { S += ws[i]; Q += wsq[i]; }
        float mu  = S / (float)DIMC;
        float var = Q / (float)DIMC - mu * mu;
        sh_mu = mu;
        sh_r  = rsqrtf(var + 1e-5f);
    }
    __syncthreads();
    const float mu = sh_mu, r = sh_r;
    float4 gg = *(const float4*)(g + c);
    float4 b4 = *(const float4*)(bb + c);
    float4 o4;
    o4.x = (v.x - mu) * r * gg.x + b4.x;
    o4.y = (v.y - mu) * r * gg.y + b4.y;
    o4.z = (v.z - mu) * r * gg.z + b4.z;
    o4.w = (v.w - mu) * r * gg.w + b4.w;
    *(float4*)(O + (size_t)row * DIMC + c) = o4;
}

// ---------------- launcher ----------------
extern "C" void kernel_launch(void* const* d_in, const int* in_sizes, int n_in,
                              void* d_out, int out_size)
{
    const float* x    = (const float*)d_in[0];
    const float* h_t  = (const float*)d_in[1];
    const float* h_a  = (const float*)d_in[2];
    const float* p    = (const float*)d_in[3];
    const float* wq   = (const float*)d_in[4];  const float* bq  = (const float*)d_in[5];
    const float* wks  = (const float*)d_in[6];  const float* bks = (const float*)d_in[7];
    const float* wvs  = (const float*)d_in[8];  const float* bvs = (const float*)d_in[9];
    const float* wka  = (const float*)d_in[10]; const float* bka = (const float*)d_in[11];
    const float* wva  = (const float*)d_in[12]; const float* bva = (const float*)d_in[13];
    const float* wkt  = (const float*)d_in[14]; const float* bkt = (const float*)d_in[15];
    const float* wvt  = (const float*)d_in[16]; const float* bvt = (const float*)d_in[17];
    const float* wo   = (const float*)d_in[18]; const float* bo  = (const float*)d_in[19];
    const float* wf   = (const float*)d_in[20]; const float* bf  = (const float*)d_in[21];
    const float* ln_g = (const float*)d_in[22];
    const float* ln_b = (const float*)d_in[23];
    const float* gate = (const float*)d_in[24];
    float* out = (float*)d_out;

    float *q_, *ktok_, *vtok_, *had_, *kada_, *vada_, *ktsk_, *vtsk_, *attn_, *y_, *yln_;
    cudaGetSymbolAddress((void**)&q_,    g_q);
    cudaGetSymbolAddress((void**)&ktok_, g_ktok);
    cudaGetSymbolAddress((void**)&vtok_, g_vtok);
    cudaGetSymbolAddress((void**)&had_,  g_had);
    cudaGetSymbolAddress((void**)&kada_, g_kada);
    cudaGetSymbolAddress((void**)&vada_, g_vada);
    cudaGetSymbolAddress((void**)&ktsk_, g_ktsk);
    cudaGetSymbolAddress((void**)&vtsk_, g_vtsk);
    cudaGetSymbolAddress((void**)&attn_, g_attn);
    cudaGetSymbolAddress((void**)&y_,    g_y);
    cudaGetSymbolAddress((void**)&yln_,  g_yln);

    const int ATTN_SMEM = (64 * 132 + 64 * 68 + 64 * 68 + 64 * 132 + 3 * 128 + 256) * 4; // 104960 B
    cudaFuncSetAttribute(attn_kernel, cudaFuncAttributeMaxDynamicSharedMemorySize, ATTN_SMEM);

    dim3 blk(256);

    // h_adapter = concat(h_a, p)
    concat_kernel<<<(NADROWS * DIMC / 4 + 255) / 256, 256>>>(h_a, p, had_);

    dim3 g1(8, 32);    // N/128, 4096/128
    dim3 g2(8, 10);    // 1280/128
    dim3 g3(8, 16);    // 2048/128

    gemm_tf32_kernel<<<g1, blk>>>(x,    wq,  bq,  nullptr, q_,    NQROWS,  DIMC, DIMC, TQ,   0);
    gemm_tf32_kernel<<<g1, blk>>>(x,    wks, bks, nullptr, ktok_, NQROWS,  DIMC, DIMC, TQ,   0);
    gemm_tf32_kernel<<<g1, blk>>>(x,    wvs, bvs, nullptr, vtok_, NQROWS,  DIMC, DIMC, 0,    0);
    gemm_tf32_kernel<<<g2, blk>>>(had_, wka, bka, nullptr, kada_, NADROWS, DIMC, DIMC, KADA, 0);
    gemm_tf32_kernel<<<g2, blk>>>(had_, wva, bva, nullptr, vada_, NADROWS, DIMC, DIMC, 0,    0);
    gemm_tf32_kernel<<<g3, blk>>>(h_t,  wkt, bkt, nullptr, ktsk_, NTKROWS, DIMC, DIMC, KTSK, 0);
    gemm_tf32_kernel<<<g3, blk>>>(h_t,  wvt, bvt, nullptr, vtsk_, NTKROWS, DIMC, DIMC, 0,    0);

    dim3 ga(TQ / 128, HEADS, BATCH);   // (8, 16, 4)
    attn_kernel<<<ga, 256, ATTN_SMEM>>>(q_, ktok_, vtok_, kada_, vada_, ktsk_, vtsk_, gate, attn_);

    gemm_tf32_kernel<<<g1, blk>>>(attn_, wo, bo, x, y_, NQROWS, DIMC, DIMC, 0, 0);
    ln_kernel<<<NQROWS, 256>>>(y_, ln_g, ln_b, yln_);
    gemm_tf32_kernel<<<g1, blk>>>(yln_, wf, bf, nullptr, out, NQROWS, DIMC, DIMC, 0, 1);
}

// round 11
// speedup vs baseline: 2.5704x; 1.6508x over previous
#include <cuda_runtime.h>
#include <math.h>
#include <stdint.h>

#define DIMC    1024
#define BATCH   4
#define TQ      1024
#define HEADS   16
#define HD      64
#define KADA    320
#define KTSK    512
#define NQROWS  (BATCH*TQ)     /* 4096 */
#define NADROWS (BATCH*KADA)   /* 1280 */
#define NTKROWS (BATCH*KTSK)   /* 2048 */
#define NTILES  29             /* 16 tok + 5 ada + 8 tsk, 64 keys each = 1856 */

// ---------------- scratch (device globals; no runtime allocation) ----------------
__device__ float g_q   [NQROWS * DIMC];
__device__ float g_ktok[NQROWS * DIMC];
__device__ float g_vtok[NQROWS * DIMC];
__device__ float g_had [NADROWS * DIMC];
__device__ float g_kada[NADROWS * DIMC];
__device__ float g_vada[NADROWS * DIMC];
__device__ float g_ktsk[NTKROWS * DIMC];
__device__ float g_vtsk[NTKROWS * DIMC];
__device__ float g_attn[NQROWS * DIMC];
__device__ float g_y   [NQROWS * DIMC];
__device__ float g_yln [NQROWS * DIMC];

// ---------------- h_adapter = concat(h_a, p) along seq ----------------
__global__ void concat_kernel(const float* __restrict__ ha,
                              const float* __restrict__ pp,
                              float* __restrict__ out)
{
    int idx = blockIdx.x * blockDim.x + threadIdx.x;     // float4 index
    const int C4 = DIMC / 4;
    const int total = NADROWS * C4;
    if (idx >= total) return;
    int c4  = idx % C4;
    int row = idx / C4;
    int b = row / KADA;
    int s = row % KADA;
    float4 v;
    if (s < 256) v = ((const float4*)ha)[(size_t)(b * 256 + s) * C4 + c4];
    else         v = ((const float4*)pp)[(size_t)(b * 64 + (s - 256)) * C4 + c4];
    ((float4*)out)[idx] = v;
}

// ---------------- tf32 helpers ----------------
__device__ __forceinline__ float tf32r(float x) {
    uint32_t u;
    asm("cvt.rna.tf32.f32 %0, %1;" : "=r"(u) : "f"(x));
    return __uint_as_float(u);
}
__device__ __forceinline__ float4 tf32r4(float4 v) {
    return make_float4(tf32r(v.x), tf32r(v.y), tf32r(v.z), tf32r(v.w));
}

#define MMA_TF32(acc, a, b)                                                    \
    asm volatile(                                                              \
        "mma.sync.aligned.m16n8k8.row.col.f32.tf32.tf32.f32 "                  \
        "{%0,%1,%2,%3}, {%4,%5,%6,%7}, {%8,%9}, {%0,%1,%2,%3};\n"              \
        : "+f"((acc)[0]), "+f"((acc)[1]), "+f"((acc)[2]), "+f"((acc)[3])       \
        : "r"((a)[0]), "r"((a)[1]), "r"((a)[2]), "r"((a)[3]),                  \
          "r"((b)[0]), "r"((b)[1]))

// ---------------- TF32 tensor-core GEMM ----------------
// C[MxN] = A[MxK] @ W[KxN] + bias (+res) (+rope/relu epilogue)
// 128x128 CTA tile, BK=16, 256 threads = 8 warps in 2(m) x 4(n) grid,
// warp tile 64x32 via mma.sync.m16n8k8.tf32. Conflict-free smem (pitch 136).
#define SPITCH 136
__global__ __launch_bounds__(256, 2)
void gemm_tf32_kernel(const float* __restrict__ A, const float* __restrict__ W,
                      const float* __restrict__ bias, const float* __restrict__ res,
                      float* __restrict__ C, int M, int K, int N,
                      int rope_seq, int do_relu)
{
    __shared__ float As[16][SPITCH];   // As[k][m]  (transposed)
    __shared__ float Bs[16][SPITCH];   // Bs[k][n]

    const int tid  = threadIdx.x;
    const int lane = tid & 31, warp = tid >> 5;
    const int grp  = lane >> 2, tig = lane & 3;
    const int wm   = (warp >> 2) * 64;    // 0 / 64
    const int wn   = (warp & 3) * 32;     // 0,32,64,96
    const int bm = blockIdx.y * 128, bn = blockIdx.x * 128;

    const int aRow = tid >> 2,  aK   = (tid & 3) << 2;   // 64 rows (+64), 4-wide k
    const int bRow = tid >> 5,  bCol = (tid & 31) << 2;  // 8 k-rows (+8), 4-wide n
    const float* Aptr = A + (size_t)(bm + aRow) * K + aK;
    const float* Wptr = W + (size_t)bRow * N + bn + bCol;

    float acc[4][4][4];
#pragma unroll
    for (int i = 0; i < 4; i++)
#pragma unroll
        for (int j = 0; j < 4; j++)
#pragma unroll
            for (int r = 0; r < 4; r++) acc[i][j][r] = 0.0f;

    float4 a0n = *(const float4*)(Aptr);
    float4 a1n = *(const float4*)(Aptr + (size_t)64 * K);
    float4 b0n = *(const float4*)(Wptr);
    float4 b1n = *(const float4*)(Wptr + (size_t)8 * N);

    for (int k0 = 0; k0 < K; k0 += 16) {
        float4 a0 = tf32r4(a0n), a1 = tf32r4(a1n);
        float4 b0 = tf32r4(b0n), b1 = tf32r4(b1n);
        As[aK + 0][aRow]      = a0.x;
        As[aK + 1][aRow]      = a0.y;
        As[aK + 2][aRow]      = a0.z;
        As[aK + 3][aRow]      = a0.w;
        As[aK + 0][aRow + 64] = a1.x;
        As[aK + 1][aRow + 64] = a1.y;
        As[aK + 2][aRow + 64] = a1.z;
        As[aK + 3][aRow + 64] = a1.w;
        *(float4*)&Bs[bRow][bCol]     = b0;
        *(float4*)&Bs[bRow + 8][bCol] = b1;
        __syncthreads();

        if (k0 + 16 < K) {
            a0n = *(const float4*)(Aptr + k0 + 16);
            a1n = *(const float4*)(Aptr + (size_t)64 * K + k0 + 16);
            b0n = *(const float4*)(Wptr + (size_t)(k0 + 16) * N);
            b1n = *(const float4*)(Wptr + (size_t)(k0 + 24) * N);
        }

#pragma unroll
        for (int kk = 0; kk < 16; kk += 8) {
            uint32_t af[4][4], bf[4][2];
#pragma unroll
            for (int mi = 0; mi < 4; mi++) {
                const int m0 = wm + mi * 16 + grp;
                af[mi][0] = __float_as_uint(As[kk + tig][m0]);
                af[mi][1] = __float_as_uint(As[kk + tig][m0 + 8]);
                af[mi][2] = __float_as_uint(As[kk + tig + 4][m0]);
                af[mi][3] = __float_as_uint(As[kk + tig + 4][m0 + 8]);
            }
#pragma unroll
            for (int ni = 0; ni < 4; ni++) {
                const int n0 = wn + ni * 8 + grp;
                bf[ni][0] = __float_as_uint(Bs[kk + tig][n0]);
                bf[ni][1] = __float_as_uint(Bs[kk + tig + 4][n0]);
            }
#pragma unroll
            for (int mi = 0; mi < 4; mi++)
#pragma unroll
                for (int ni = 0; ni < 4; ni++)
                    MMA_TF32(acc[mi][ni], af[mi], bf[ni]);
        }
        __syncthreads();
    }

    // epilogue: each thread owns pairs (col, col+1) with col even -> rope pairs align.
#pragma unroll
    for (int mi = 0; mi < 4; mi++) {
#pragma unroll
        for (int half = 0; half < 2; half++) {
            const int gRow = bm + wm + mi * 16 + grp + half * 8;
            const int pos = rope_seq ? (gRow % rope_seq) : 0;
            const float fp = (float)pos;
#pragma unroll
            for (int ni = 0; ni < 4; ni++) {
                const int gCol = bn + wn + ni * 8 + tig * 2;
                float v0 = acc[mi][ni][half * 2 + 0] + bias[gCol];
                float v1 = acc[mi][ni][half * 2 + 1] + bias[gCol + 1];
                if (res) {
                    const float* rr = res + (size_t)gRow * N + gCol;
                    v0 += rr[0];
                    v1 += rr[1];
                }
                if (rope_seq) {
                    const int d  = gCol & 63;       // even
                    const int f0 = d & 31;          // concat tables: freq idx = d % 32
                    float inv0 = exp2f((float)f0       * -0.41524101186409203f);
                    float inv1 = exp2f((float)(f0 + 1) * -0.41524101186409203f);
                    float s0, c0, s1, c1;
                    sincosf(fp * inv0, &s0, &c0);
                    sincosf(fp * inv1, &s1, &c1);
                    float e = v0, o = v1;
                    v0 = e * c0 - o * s0;
                    v1 = o * c1 + e * s1;
                }
                if (do_relu) {
                    v0 = fmaxf(v0, 0.0f);
                    v1 = fmaxf(v1, 0.0f);
                }
                *(float2*)(C + (size_t)gRow * N + gCol) = make_float2(v0, v1);
            }
        }
    }
}

// ---------------- tensor-core flash attention ----------------
// Block = (qtile, head, batch); 128 q rows, 64-key tiles, online softmax.
// 8 warps = 4(m:q) x 2(n), warp tile 32x32; both S=Q·K^T and O+=P·V on tf32 mma.
// Smem pitches chosen conflict-free for fragment loads:
//   Qs/Ss pitch 68 (bank = 4*grp+tig), Vs pitch 72 (bank = 8*tig+grp), Ks pitch 68.
#define QP 68
#define KP 68
#define VP 72
#define SP 68
__global__ __launch_bounds__(256, 2)
void attn_tc_kernel(const float* __restrict__ q,
                    const float* __restrict__ ktok, const float* __restrict__ vtok,
                    const float* __restrict__ kada, const float* __restrict__ vada,
                    const float* __restrict__ ktsk, const float* __restrict__ vtsk,
                    const float* __restrict__ gate, float* __restrict__ out)
{
    extern __shared__ float sm[];
    float* Qs   = sm;                 // [q][d]    128 x QP
    float* Ks   = Qs + 128 * QP;      // [key][d]  64 x KP
    float* Vs   = Ks + 64 * KP;       // [key][d]  64 x VP
    float* Ss   = Vs + 64 * VP;       // [q][key]  128 x SP
    float* sm_m = Ss + 128 * SP;      // 128
    float* sm_l = sm_m + 128;         // 128
    float* sm_a = sm_l + 128;         // 128
    float* red  = sm_a + 128;         // 256

    const int b = blockIdx.z, h = blockIdx.y, qt = blockIdx.x;
    const int tid  = threadIdx.x;
    const int lane = tid & 31, warp = tid >> 5;
    const int grp  = lane >> 2, tig = lane & 3;
    const int wmq  = (warp >> 1) * 32;   // q offset: 0,32,64,96
    const int wn   = (warp & 1) * 32;    // key/d offset: 0,32
    const float gfac = tanhf(gate[0]);

    // load Q tile (128 x 64) row-major, tf32-rounded
    const float* qbase = q + ((size_t)(b * TQ + qt * 128)) * DIMC + h * HD;
    for (int f = tid; f < 2048; f += 256) {
        int r = f >> 4, d4 = (f & 15) << 2;
        *(float4*)&Qs[r * QP + d4] = tf32r4(*(const float4*)(qbase + (size_t)r * DIMC + d4));
    }
    if (tid < 128) { sm_m[tid] = -1e30f; sm_l[tid] = 0.0f; }

    float oacc[2][4][4];
#pragma unroll
    for (int i = 0; i < 2; i++)
#pragma unroll
        for (int j = 0; j < 4; j++)
#pragma unroll
            for (int r = 0; r < 4; r++) oacc[i][j][r] = 0.0f;
    __syncthreads();

    for (int kt = 0; kt < NTILES; kt++) {
        const float *kp, *vp;
        float sscale;
        if (kt < 16) {
            size_t off = ((size_t)(b * TQ + kt * 64)) * DIMC + h * HD;
            kp = ktok + off; vp = vtok + off; sscale = 0.125f;
        } else if (kt < 21) {
            size_t off = ((size_t)(b * KADA + (kt - 16) * 64)) * DIMC + h * HD;
            kp = kada + off; vp = vada + off; sscale = 0.125f;
        } else {
            size_t off = ((size_t)(b * KTSK + (kt - 21) * 64)) * DIMC + h * HD;
            kp = ktsk + off; vp = vtsk + off; sscale = 0.125f * gfac;
        }

        for (int f = tid; f < 1024; f += 256) {
            int r = f >> 4, d4 = (f & 15) << 2;
            *(float4*)&Ks[r * KP + d4] = tf32r4(*(const float4*)(kp + (size_t)r * DIMC + d4));
            *(float4*)&Vs[r * VP + d4] = tf32r4(*(const float4*)(vp + (size_t)r * DIMC + d4));
        }
        __syncthreads();

        // ---- S = Q · K^T  (m=128 q, n=64 keys, k=64 d) ----
        float sacc[2][4][4];
#pragma unroll
        for (int i = 0; i < 2; i++)
#pragma unroll
            for (int j = 0; j < 4; j++)
#pragma unroll
                for (int r = 0; r < 4; r++) sacc[i][j][r] = 0.0f;

#pragma unroll
        for (int kk = 0; kk < 64; kk += 8) {
            uint32_t af[2][4], bf[4][2];
#pragma unroll
            for (int mi = 0; mi < 2; mi++) {
                const int m0 = wmq + mi * 16 + grp;
                af[mi][0] = __float_as_uint(Qs[m0 * QP + kk + tig]);
                af[mi][1] = __float_as_uint(Qs[(m0 + 8) * QP + kk + tig]);
                af[mi][2] = __float_as_uint(Qs[m0 * QP + kk + tig + 4]);
                af[mi][3] = __float_as_uint(Qs[(m0 + 8) * QP + kk + tig + 4]);
            }
#pragma unroll
            for (int ni = 0; ni < 4; ni++) {
                const int n0 = wn + ni * 8 + grp;       // key index
                bf[ni][0] = __float_as_uint(Ks[n0 * KP + kk + tig]);
                bf[ni][1] = __float_as_uint(Ks[n0 * KP + kk + tig + 4]);
            }
#pragma unroll
            for (int mi = 0; mi < 2; mi++)
#pragma unroll
                for (int ni = 0; ni < 4; ni++)
                    MMA_TF32(sacc[mi][ni], af[mi], bf[ni]);
        }
#pragma unroll
        for (int mi = 0; mi < 2; mi++) {
            const int r0 = wmq + mi * 16 + grp;
#pragma unroll
            for (int ni = 0; ni < 4; ni++) {
                const int col = wn + ni * 8 + tig * 2;
                *(float2*)&Ss[r0 * SP + col] =
                    make_float2(sacc[mi][ni][0] * sscale, sacc[mi][ni][1] * sscale);
                *(float2*)&Ss[(r0 + 8) * SP + col] =
                    make_float2(sacc[mi][ni][2] * sscale, sacc[mi][ni][3] * sscale);
            }
        }
        __syncthreads();

        // ---- online softmax per q row (2 threads per row, 32 keys each) ----
        const int qc = tid >> 1, part = tid & 1;
        float* srow = &Ss[qc * SP + part * 32];
        float lm = -1e30f;
#pragma unroll
        for (int k = 0; k < 32; k++) lm = fmaxf(lm, srow[k]);
        red[qc * 2 + part] = lm;
        __syncthreads();
        if (part == 0) {
            float mt = fmaxf(red[qc * 2], red[qc * 2 + 1]);
            float mn = fmaxf(sm_m[qc], mt);
            sm_a[qc] = __expf(sm_m[qc] - mn);
            sm_m[qc] = mn;
        }
        __syncthreads();
        const float mn = sm_m[qc];
        float lsum = 0.0f;
#pragma unroll
        for (int k = 0; k < 32; k++) {
            float pv = tf32r(__expf(srow[k] - mn));   // round so PV mma matches l
            srow[k] = pv;
            lsum += pv;
        }
        red[qc * 2 + part] = lsum;
        __syncthreads();
        if (part == 0)
            sm_l[qc] = sm_l[qc] * sm_a[qc] + red[qc * 2] + red[qc * 2 + 1];
        __syncthreads();

        // ---- O = O*alpha + P · V  (m=128 q, n=64 d, k=64 keys) ----
#pragma unroll
        for (int mi = 0; mi < 2; mi++) {
            const float a0 = sm_a[wmq + mi * 16 + grp];
            const float a1 = sm_a[wmq + mi * 16 + grp + 8];
#pragma unroll
            for (int ni = 0; ni < 4; ni++) {
                oacc[mi][ni][0] *= a0;
                oacc[mi][ni][1] *= a0;
                oacc[mi][ni][2] *= a1;
                oacc[mi][ni][3] *= a1;
            }
        }
#pragma unroll
        for (int kk = 0; kk < 64; kk += 8) {
            uint32_t af[2][4], bf[4][2];
#pragma unroll
            for (int mi = 0; mi < 2; mi++) {
                const int m0 = wmq + mi * 16 + grp;
                af[mi][0] = __float_as_uint(Ss[m0 * SP + kk + tig]);
                af[mi][1] = __float_as_uint(Ss[(m0 + 8) * SP + kk + tig]);
                af[mi][2] = __float_as_uint(Ss[m0 * SP + kk + tig + 4]);
                af[mi][3] = __float_as_uint(Ss[(m0 + 8) * SP + kk + tig + 4]);
            }
#pragma unroll
            for (int ni = 0; ni < 4; ni++) {
                const int n0 = wn + ni * 8 + grp;       // d index
                bf[ni][0] = __float_as_uint(Vs[(kk + tig) * VP + n0]);
                bf[ni][1] = __float_as_uint(Vs[(kk + tig + 4) * VP + n0]);
            }
#pragma unroll
            for (int mi = 0; mi < 2; mi++)
#pragma unroll
                for (int ni = 0; ni < 4; ni++)
                    MMA_TF32(oacc[mi][ni], af[mi], bf[ni]);
        }
        __syncthreads();
    }

    // epilogue: normalize and write
    float* obase = out + ((size_t)(b * TQ + qt * 128)) * DIMC + h * HD;
#pragma unroll
    for (int mi = 0; mi < 2; mi++) {
        const int r0 = wmq + mi * 16 + grp;
        const float inv0 = 1.0f / sm_l[r0];
        const float inv1 = 1.0f / sm_l[r0 + 8];
#pragma unroll
        for (int ni = 0; ni < 4; ni++) {
            const int col = wn + ni * 8 + tig * 2;
            *(float2*)(obase + (size_t)r0 * DIMC + col) =
                make_float2(oacc[mi][ni][0] * inv0, oacc[mi][ni][1] * inv0);
            *(float2*)(obase + (size_t)(r0 + 8) * DIMC + col) =
                make_float2(oacc[mi][ni][2] * inv1, oacc[mi][ni][3] * inv1);
        }
    }
}

// ---------------- LayerNorm over C=1024, one block per row ----------------
__global__ __launch_bounds__(256)
void ln_kernel(const float* __restrict__ Y, const float* __restrict__ g,
               const float* __restrict__ bb, float* __restrict__ O)
{
    const int row = blockIdx.x;
    const int tid = threadIdx.x;
    const int c = tid * 4;
    float4 v = *(const float4*)(Y + (size_t)row * DIMC + c);
    float s  = v.x + v.y + v.z + v.w;
    float sq = v.x * v.x + v.y * v.y + v.z * v.z + v.w * v.w;
#pragma unroll
    for (int off = 16; off; off >>= 1) {
        s  += __shfl_xor_sync(0xffffffffu, s, off);
        sq += __shfl_xor_sync(0xffffffffu, sq, off);
    }
    __shared__ float ws[8], wsq[8];
    __shared__ float sh_mu, sh_r;
    const int w = tid >> 5, l = tid & 31;
    if (l == 0) { ws[w] = s; wsq[w] = sq; }
    __syncthreads();
    if (tid == 0) {
        float S = 0.0f, Q = 0.0f;
#pragma unroll
        for (int i = 0; i < 8; i++) { S += ws[i]; Q += wsq[i]; }
        float mu  = S / (float)DIMC;
        float var = Q / (float)DIMC - mu * mu;
        sh_mu = mu;
        sh_r  = rsqrtf(var + 1e-5f);
    }
    __syncthreads();
    const float mu = sh_mu, r = sh_r;
    float4 gg = *(const float4*)(g + c);
    float4 b4 = *(const float4*)(bb + c);
    float4 o4;
    o4.x = (v.x - mu) * r * gg.x + b4.x;
    o4.y = (v.y - mu) * r * gg.y + b4.y;
    o4.z = (v.z - mu) * r * gg.z + b4.z;
    o4.w = (v.w - mu) * r * gg.w + b4.w;
    *(float4*)(O + (size_t)row * DIMC + c) = o4;
}

// ---------------- launcher ----------------
extern "C" void kernel_launch(void* const* d_in, const int* in_sizes, int n_in,
                              void* d_out, int out_size)
{
    const float* x    = (const float*)d_in[0];
    const float* h_t  = (const float*)d_in[1];
    const float* h_a  = (const float*)d_in[2];
    const float* p    = (const float*)d_in[3];
    const float* wq   = (const float*)d_in[4];  const float* bq  = (const float*)d_in[5];
    const float* wks  = (const float*)d_in[6];  const float* bks = (const float*)d_in[7];
    const float* wvs  = (const float*)d_in[8];  const float* bvs = (const float*)d_in[9];
    const float* wka  = (const float*)d_in[10]; const float* bka = (const float*)d_in[11];
    const float* wva  = (const float*)d_in[12]; const float* bva = (const float*)d_in[13];
    const float* wkt  = (const float*)d_in[14]; const float* bkt = (const float*)d_in[15];
    const float* wvt  = (const float*)d_in[16]; const float* bvt = (const float*)d_in[17];
    const float* wo   = (const float*)d_in[18]; const float* bo  = (const float*)d_in[19];
    const float* wf   = (const float*)d_in[20]; const float* bf  = (const float*)d_in[21];
    const float* ln_g = (const float*)d_in[22];
    const float* ln_b = (const float*)d_in[23];
    const float* gate = (const float*)d_in[24];
    float* out = (float*)d_out;

    float *q_, *ktok_, *vtok_, *had_, *kada_, *vada_, *ktsk_, *vtsk_, *attn_, *y_, *yln_;
    cudaGetSymbolAddress((void**)&q_,    g_q);
    cudaGetSymbolAddress((void**)&ktok_, g_ktok);
    cudaGetSymbolAddress((void**)&vtok_, g_vtok);
    cudaGetSymbolAddress((void**)&had_,  g_had);
    cudaGetSymbolAddress((void**)&kada_, g_kada);
    cudaGetSymbolAddress((void**)&vada_, g_vada);
    cudaGetSymbolAddress((void**)&ktsk_, g_ktsk);
    cudaGetSymbolAddress((void**)&vtsk_, g_vtsk);
    cudaGetSymbolAddress((void**)&attn_, g_attn);
    cudaGetSymbolAddress((void**)&y_,    g_y);
    cudaGetSymbolAddress((void**)&yln_,  g_yln);

    const int ATTN_SMEM = (128 * QP + 64 * KP + 64 * VP + 128 * SP + 3 * 128 + 256) * 4; // 108032 B
    cudaFuncSetAttribute(attn_tc_kernel, cudaFuncAttributeMaxDynamicSharedMemorySize, ATTN_SMEM);

    dim3 blk(256);

    // h_adapter = concat(h_a, p)
    concat_kernel<<<(NADROWS * DIMC / 4 + 255) / 256, 256>>>(h_a, p, had_);

    dim3 g1(8, 32);    // N/128, 4096/128
    dim3 g2(8, 10);    // 1280/128
    dim3 g3(8, 16);    // 2048/128

    gemm_tf32_kernel<<<g1, blk>>>(x,    wq,  bq,  nullptr, q_,    NQROWS,  DIMC, DIMC, TQ,   0);
    gemm_tf32_kernel<<<g1, blk>>>(x,    wks, bks, nullptr, ktok_, NQROWS,  DIMC, DIMC, TQ,   0);
    gemm_tf32_kernel<<<g1, blk>>>(x,    wvs, bvs, nullptr, vtok_, NQROWS,  DIMC, DIMC, 0,    0);
    gemm_tf32_kernel<<<g2, blk>>>(had_, wka, bka, nullptr, kada_, NADROWS, DIMC, DIMC, KADA, 0);
    gemm_tf32_kernel<<<g2, blk>>>(had_, wva, bva, nullptr, vada_, NADROWS, DIMC, DIMC, 0,    0);
    gemm_tf32_kernel<<<g3, blk>>>(h_t,  wkt, bkt, nullptr, ktsk_, NTKROWS, DIMC, DIMC, KTSK, 0);
    gemm_tf32_kernel<<<g3, blk>>>(h_t,  wvt, bvt, nullptr, vtsk_, NTKROWS, DIMC, DIMC, 0,    0);

    dim3 ga(TQ / 128, HEADS, BATCH);   // (8, 16, 4)
    attn_tc_kernel<<<ga, 256, ATTN_SMEM>>>(q_, ktok_, vtok_, kada_, vada_, ktsk_, vtsk_, gate, attn_);

    gemm_tf32_kernel<<<g1, blk>>>(attn_, wo, bo, x, y_, NQROWS, DIMC, DIMC, 0, 0);
    ln_kernel<<<NQROWS, 256>>>(y_, ln_g, ln_b, yln_);
    gemm_tf32_kernel<<<g1, blk>>>(yln_, wf, bf, nullptr, out, NQROWS, DIMC, DIMC, 0, 1);
}

// round 12
// speedup vs baseline: 2.9283x; 1.1392x over previous
#include <cuda_runtime.h>
#include <math.h>
#include <stdint.h>

#define DIMC    1024
#define BATCH   4
#define TQ      1024
#define HEADS   16
#define HD      64
#define KADA    320
#define KTSK    512
#define NQROWS  (BATCH*TQ)     /* 4096 */
#define NADROWS (BATCH*KADA)   /* 1280 */
#define NTKROWS (BATCH*KTSK)   /* 2048 */
#define NTILES  29             /* 16 tok + 5 ada + 8 tsk, 64 keys each = 1856 */

// ---------------- scratch (device globals; no runtime allocation) ----------------
__device__ float g_q   [NQROWS * DIMC];
__device__ float g_ktok[NQROWS * DIMC];
__device__ float g_vtok[NQROWS * DIMC];
__device__ float g_had [NADROWS * DIMC];
__device__ float g_kada[NADROWS * DIMC];
__device__ float g_vada[NADROWS * DIMC];
__device__ float g_ktsk[NTKROWS * DIMC];
__device__ float g_vtsk[NTKROWS * DIMC];
__device__ float g_attn[NQROWS * DIMC];
__device__ float g_y   [NQROWS * DIMC];
__device__ float g_yln [NQROWS * DIMC];

// ---------------- h_adapter = concat(h_a, p) along seq ----------------
__global__ void concat_kernel(const float* __restrict__ ha,
                              const float* __restrict__ pp,
                              float* __restrict__ out)
{
    int idx = blockIdx.x * blockDim.x + threadIdx.x;     // float4 index
    const int C4 = DIMC / 4;
    const int total = NADROWS * C4;
    if (idx >= total) return;
    int c4  = idx % C4;
    int row = idx / C4;
    int b = row / KADA;
    int s = row % KADA;
    float4 v;
    if (s < 256) v = ((const float4*)ha)[(size_t)(b * 256 + s) * C4 + c4];
    else         v = ((const float4*)pp)[(size_t)(b * 64 + (s - 256)) * C4 + c4];
    ((float4*)out)[idx] = v;
}

// ---------------- tf32 helpers ----------------
__device__ __forceinline__ float tf32r(float x) {
    uint32_t u;
    asm("cvt.rna.tf32.f32 %0, %1;" : "=r"(u) : "f"(x));
    return __uint_as_float(u);
}
__device__ __forceinline__ float4 tf32r4(float4 v) {
    return make_float4(tf32r(v.x), tf32r(v.y), tf32r(v.z), tf32r(v.w));
}

#define MMA_TF32(acc, a, b)                                                    \
    asm volatile(                                                              \
        "mma.sync.aligned.m16n8k8.row.col.f32.tf32.tf32.f32 "                  \
        "{%0,%1,%2,%3}, {%4,%5,%6,%7}, {%8,%9}, {%0,%1,%2,%3};\n"              \
        : "+f"((acc)[0]), "+f"((acc)[1]), "+f"((acc)[2]), "+f"((acc)[3])       \
        : "r"((a)[0]), "r"((a)[1]), "r"((a)[2]), "r"((a)[3]),                  \
          "r"((b)[0]), "r"((b)[1]))

// ---------------- TF32 tensor-core GEMM core (double-buffered smem) ----------
// C[MxN] = A[MxK] @ W[KxN] + bias (+res) (+rope/relu epilogue)
// 128x128 CTA tile, BK=16, 256 threads = 8 warps in 2(m) x 4(n) grid,
// warp tile 64x32 via mma.sync.m16n8k8.tf32. Conflict-free smem (pitch 136).
#define SPITCH 136
#define SLAB   (16 * SPITCH)

__device__ __forceinline__ void gemm_body(
    const float* __restrict__ A, const float* __restrict__ W,
    const float* __restrict__ bias, const float* __restrict__ res,
    float* __restrict__ C, int K, int N, int rope_seq, int do_relu,
    float* __restrict__ AsB, float* __restrict__ BsB)
{
    const int tid  = threadIdx.x;
    const int lane = tid & 31, warp = tid >> 5;
    const int grp  = lane >> 2, tig = lane & 3;
    const int wm   = (warp >> 2) * 64;    // 0 / 64
    const int wn   = (warp & 3) * 32;     // 0,32,64,96
    const int bm = blockIdx.y * 128, bn = blockIdx.x * 128;

    const int aRow = tid >> 2,  aK   = (tid & 3) << 2;   // 64 rows (+64), 4-wide k
    const int bRow = tid >> 5,  bCol = (tid & 31) << 2;  // 8 k-rows (+8), 4-wide n
    const float* Aptr = A + (size_t)(bm + aRow) * K + aK;
    const float* Wptr = W + (size_t)bRow * N + bn + bCol;

    float acc[4][4][4];
#pragma unroll
    for (int i = 0; i < 4; i++)
#pragma unroll
        for (int j = 0; j < 4; j++)
#pragma unroll
            for (int r = 0; r < 4; r++) acc[i][j][r] = 0.0f;

    // prologue: load + store slab 0
    {
        float4 a0 = tf32r4(*(const float4*)(Aptr));
        float4 a1 = tf32r4(*(const float4*)(Aptr + (size_t)64 * K));
        float4 b0 = tf32r4(*(const float4*)(Wptr));
        float4 b1 = tf32r4(*(const float4*)(Wptr + (size_t)8 * N));
        AsB[(aK + 0) * SPITCH + aRow]      = a0.x;
        AsB[(aK + 1) * SPITCH + aRow]      = a0.y;
        AsB[(aK + 2) * SPITCH + aRow]      = a0.z;
        AsB[(aK + 3) * SPITCH + aRow]      = a0.w;
        AsB[(aK + 0) * SPITCH + aRow + 64] = a1.x;
        AsB[(aK + 1) * SPITCH + aRow + 64] = a1.y;
        AsB[(aK + 2) * SPITCH + aRow + 64] = a1.z;
        AsB[(aK + 3) * SPITCH + aRow + 64] = a1.w;
        *(float4*)&BsB[bRow * SPITCH + bCol]       = b0;
        *(float4*)&BsB[(bRow + 8) * SPITCH + bCol] = b1;
    }
    __syncthreads();

    int buf = 0;
    for (int k0 = 0; k0 < K; k0 += 16) {
        float4 a0n, a1n, b0n, b1n;
        const bool more = (k0 + 16 < K);
        if (more) {
            a0n = *(const float4*)(Aptr + k0 + 16);
            a1n = *(const float4*)(Aptr + (size_t)64 * K + k0 + 16);
            b0n = *(const float4*)(Wptr + (size_t)(k0 + 16) * N);
            b1n = *(const float4*)(Wptr + (size_t)(k0 + 24) * N);
        }

        const float* As = AsB + buf * SLAB;
        const float* Bs = BsB + buf * SLAB;
#pragma unroll
        for (int kk = 0; kk < 16; kk += 8) {
            uint32_t af[4][4], bf[4][2];
#pragma unroll
            for (int mi = 0; mi < 4; mi++) {
                const int m0 = wm + mi * 16 + grp;
                af[mi][0] = __float_as_uint(As[(kk + tig) * SPITCH + m0]);
                af[mi][1] = __float_as_uint(As[(kk + tig) * SPITCH + m0 + 8]);
                af[mi][2] = __float_as_uint(As[(kk + tig + 4) * SPITCH + m0]);
                af[mi][3] = __float_as_uint(As[(kk + tig + 4) * SPITCH + m0 + 8]);
            }
#pragma unroll
            for (int ni = 0; ni < 4; ni++) {
                const int n0 = wn + ni * 8 + grp;
                bf[ni][0] = __float_as_uint(Bs[(kk + tig) * SPITCH + n0]);
                bf[ni][1] = __float_as_uint(Bs[(kk + tig + 4) * SPITCH + n0]);
            }
#pragma unroll
            for (int mi = 0; mi < 4; mi++)
#pragma unroll
                for (int ni = 0; ni < 4; ni++)
                    MMA_TF32(acc[mi][ni], af[mi], bf[ni]);
        }

        if (more) {
            float* Asn = AsB + (buf ^ 1) * SLAB;
            float* Bsn = BsB + (buf ^ 1) * SLAB;
            float4 a0 = tf32r4(a0n), a1 = tf32r4(a1n);
            float4 b0 = tf32r4(b0n), b1 = tf32r4(b1n);
            Asn[(aK + 0) * SPITCH + aRow]      = a0.x;
            Asn[(aK + 1) * SPITCH + aRow]      = a0.y;
            Asn[(aK + 2) * SPITCH + aRow]      = a0.z;
            Asn[(aK + 3) * SPITCH + aRow]      = a0.w;
            Asn[(aK + 0) * SPITCH + aRow + 64] = a1.x;
            Asn[(aK + 1) * SPITCH + aRow + 64] = a1.y;
            Asn[(aK + 2) * SPITCH + aRow + 64] = a1.z;
            Asn[(aK + 3) * SPITCH + aRow + 64] = a1.w;
            *(float4*)&Bsn[bRow * SPITCH + bCol]       = b0;
            *(float4*)&Bsn[(bRow + 8) * SPITCH + bCol] = b1;
            __syncthreads();
            buf ^= 1;
        }
    }

    // epilogue: each thread owns pairs (col, col+1) with col even -> rope pairs align.
#pragma unroll
    for (int mi = 0; mi < 4; mi++) {
#pragma unroll
        for (int half = 0; half < 2; half++) {
            const int gRow = bm + wm + mi * 16 + grp + half * 8;
            const int pos = rope_seq ? (gRow % rope_seq) : 0;
            const float fp = (float)pos;
#pragma unroll
            for (int ni = 0; ni < 4; ni++) {
                const int gCol = bn + wn + ni * 8 + tig * 2;
                float v0 = acc[mi][ni][half * 2 + 0] + bias[gCol];
                float v1 = acc[mi][ni][half * 2 + 1] + bias[gCol + 1];
                if (res) {
                    const float* rr = res + (size_t)gRow * N + gCol;
                    v0 += rr[0];
                    v1 += rr[1];
                }
                if (rope_seq) {
                    const int d  = gCol & 63;       // even
                    const int f0 = d & 31;          // concat tables: freq idx = d % 32
                    float inv0 = exp2f((float)f0       * -0.41524101186409203f);
                    float inv1 = exp2f((float)(f0 + 1) * -0.41524101186409203f);
                    float s0, c0, s1, c1;
                    sincosf(fp * inv0, &s0, &c0);
                    sincosf(fp * inv1, &s1, &c1);
                    float e = v0, o = v1;
                    v0 = e * c0 - o * s0;
                    v1 = o * c1 + e * s1;
                }
                if (do_relu) {
                    v0 = fmaxf(v0, 0.0f);
                    v1 = fmaxf(v1, 0.0f);
                }
                *(float2*)(C + (size_t)gRow * N + gCol) = make_float2(v0, v1);
            }
        }
    }
}

__global__ __launch_bounds__(256, 2)
void gemm_tf32_kernel(const float* __restrict__ A, const float* __restrict__ W,
                      const float* __restrict__ bias, const float* __restrict__ res,
                      float* __restrict__ C, int K, int N,
                      int rope_seq, int do_relu)
{
    __shared__ float AsB[2 * SLAB];
    __shared__ float BsB[2 * SLAB];
    gemm_body(A, W, bias, res, C, K, N, rope_seq, do_relu, AsB, BsB);
}

// fused sibling projections: blockIdx.z selects (W, bias, C, rope)
__global__ __launch_bounds__(256, 2)
void gemm3_tf32_kernel(const float* __restrict__ A,
                       const float* __restrict__ W0, const float* __restrict__ W1,
                       const float* __restrict__ W2,
                       const float* __restrict__ b0, const float* __restrict__ b1,
                       const float* __restrict__ b2,
                       float* __restrict__ C0, float* __restrict__ C1,
                       float* __restrict__ C2,
                       int K, int N, int rope0, int rope1, int rope2)
{
    __shared__ float AsB[2 * SLAB];
    __shared__ float BsB[2 * SLAB];
    const float* W;  const float* bias;  float* C;  int rope;
    if (blockIdx.z == 0)      { W = W0; bias = b0; C = C0; rope = rope0; }
    else if (blockIdx.z == 1) { W = W1; bias = b1; C = C1; rope = rope1; }
    else                      { W = W2; bias = b2; C = C2; rope = rope2; }
    gemm_body(A, W, bias, nullptr, C, K, N, rope, 0, AsB, BsB);
}

// ---------------- tensor-core flash attention ----------------
// Block = (qtile, head, batch); 128 q rows, 64-key tiles, online softmax.
// 8 warps = 4(m:q) x 2(n), warp tile 32x32; both S=Q·K^T and O+=P·V on tf32 mma.
#define QP 68
#define KP 68
#define VP 72
#define SP 68
__global__ __launch_bounds__(256, 2)
void attn_tc_kernel(const float* __restrict__ q,
                    const float* __restrict__ ktok, const float* __restrict__ vtok,
                    const float* __restrict__ kada, const float* __restrict__ vada,
                    const float* __restrict__ ktsk, const float* __restrict__ vtsk,
                    const float* __restrict__ gate, float* __restrict__ out)
{
    extern __shared__ float sm[];
    float* Qs   = sm;                 // [q][d]    128 x QP
    float* Ks   = Qs + 128 * QP;      // [key][d]  64 x KP
    float* Vs   = Ks + 64 * KP;       // [key][d]  64 x VP
    float* Ss   = Vs + 64 * VP;       // [q][key]  128 x SP
    float* sm_m = Ss + 128 * SP;      // 128
    float* sm_l = sm_m + 128;         // 128
    float* sm_a = sm_l + 128;         // 128
    float* red  = sm_a + 128;         // 256

    const int b = blockIdx.z, h = blockIdx.y, qt = blockIdx.x;
    const int tid  = threadIdx.x;
    const int lane = tid & 31, warp = tid >> 5;
    const int grp  = lane >> 2, tig = lane & 3;
    const int wmq  = (warp >> 1) * 32;   // q offset: 0,32,64,96
    const int wn   = (warp & 1) * 32;    // key/d offset: 0,32
    const float gfac = tanhf(gate[0]);

    // load Q tile (128 x 64) row-major, tf32-rounded
    const float* qbase = q + ((size_t)(b * TQ + qt * 128)) * DIMC + h * HD;
    for (int f = tid; f < 2048; f += 256) {
        int r = f >> 4, d4 = (f & 15) << 2;
        *(float4*)&Qs[r * QP + d4] = tf32r4(*(const float4*)(qbase + (size_t)r * DIMC + d4));
    }
    if (tid < 128) { sm_m[tid] = -1e30f; sm_l[tid] = 0.0f; }

    float oacc[2][4][4];
#pragma unroll
    for (int i = 0; i < 2; i++)
#pragma unroll
        for (int j = 0; j < 4; j++)
#pragma unroll
            for (int r = 0; r < 4; r++) oacc[i][j][r] = 0.0f;
    __syncthreads();

    for (int kt = 0; kt < NTILES; kt++) {
        const float *kp, *vp;
        float sscale;
        if (kt < 16) {
            size_t off = ((size_t)(b * TQ + kt * 64)) * DIMC + h * HD;
            kp = ktok + off; vp = vtok + off; sscale = 0.125f;
        } else if (kt < 21) {
            size_t off = ((size_t)(b * KADA + (kt - 16) * 64)) * DIMC + h * HD;
            kp = kada + off; vp = vada + off; sscale = 0.125f;
        } else {
            size_t off = ((size_t)(b * KTSK + (kt - 21) * 64)) * DIMC + h * HD;
            kp = ktsk + off; vp = vtsk + off; sscale = 0.125f * gfac;
        }

        for (int f = tid; f < 1024; f += 256) {
            int r = f >> 4, d4 = (f & 15) << 2;
            *(float4*)&Ks[r * KP + d4] = tf32r4(*(const float4*)(kp + (size_t)r * DIMC + d4));
            *(float4*)&Vs[r * VP + d4] = tf32r4(*(const float4*)(vp + (size_t)r * DIMC + d4));
        }
        __syncthreads();

        // ---- S = Q · K^T  (m=128 q, n=64 keys, k=64 d) ----
        float sacc[2][4][4];
#pragma unroll
        for (int i = 0; i < 2; i++)
#pragma unroll
            for (int j = 0; j < 4; j++)
#pragma unroll
                for (int r = 0; r < 4; r++) sacc[i][j][r] = 0.0f;

#pragma unroll
        for (int kk = 0; kk < 64; kk += 8) {
            uint32_t af[2][4], bf[4][2];
#pragma unroll
            for (int mi = 0; mi < 2; mi++) {
                const int m0 = wmq + mi * 16 + grp;
                af[mi][0] = __float_as_uint(Qs[m0 * QP + kk + tig]);
                af[mi][1] = __float_as_uint(Qs[(m0 + 8) * QP + kk + tig]);
                af[mi][2] = __float_as_uint(Qs[m0 * QP + kk + tig + 4]);
                af[mi][3] = __float_as_uint(Qs[(m0 + 8) * QP + kk + tig + 4]);
            }
#pragma unroll
            for (int ni = 0; ni < 4; ni++) {
                const int n0 = wn + ni * 8 + grp;       // key index
                bf[ni][0] = __float_as_uint(Ks[n0 * KP + kk + tig]);
                bf[ni][1] = __float_as_uint(Ks[n0 * KP + kk + tig + 4]);
            }
#pragma unroll
            for (int mi = 0; mi < 2; mi++)
#pragma unroll
                for (int ni = 0; ni < 4; ni++)
                    MMA_TF32(sacc[mi][ni], af[mi], bf[ni]);
        }
#pragma unroll
        for (int mi = 0; mi < 2; mi++) {
            const int r0 = wmq + mi * 16 + grp;
#pragma unroll
            for (int ni = 0; ni < 4; ni++) {
                const int col = wn + ni * 8 + tig * 2;
                *(float2*)&Ss[r0 * SP + col] =
                    make_float2(sacc[mi][ni][0] * sscale, sacc[mi][ni][1] * sscale);
                *(float2*)&Ss[(r0 + 8) * SP + col] =
                    make_float2(sacc[mi][ni][2] * sscale, sacc[mi][ni][3] * sscale);
            }
        }
        __syncthreads();

        // ---- online softmax per q row (2 threads per row, 32 keys each) ----
        const int qc = tid >> 1, part = tid & 1;
        float* srow = &Ss[qc * SP + part * 32];
        float lm = -1e30f;
#pragma unroll
        for (int k = 0; k < 32; k++) lm = fmaxf(lm, srow[k]);
        red[qc * 2 + part] = lm;
        __syncthreads();
        if (part == 0) {
            float mt = fmaxf(red[qc * 2], red[qc * 2 + 1]);
            float mn = fmaxf(sm_m[qc], mt);
            sm_a[qc] = __expf(sm_m[qc] - mn);
            sm_m[qc] = mn;
        }
        __syncthreads();
        const float mn = sm_m[qc];
        float lsum = 0.0f;
#pragma unroll
        for (int k = 0; k < 32; k++) {
            float pv = tf32r(__expf(srow[k] - mn));   // round so PV mma matches l
            srow[k] = pv;
            lsum += pv;
        }
        red[qc * 2 + part] = lsum;
        __syncthreads();
        if (part == 0)
            sm_l[qc] = sm_l[qc] * sm_a[qc] + red[qc * 2] + red[qc * 2 + 1];
        __syncthreads();

        // ---- O = O*alpha + P · V  (m=128 q, n=64 d, k=64 keys) ----
#pragma unroll
        for (int mi = 0; mi < 2; mi++) {
            const float a0 = sm_a[wmq + mi * 16 + grp];
            const float a1 = sm_a[wmq + mi * 16 + grp + 8];
#pragma unroll
            for (int ni = 0; ni < 4; ni++) {
                oacc[mi][ni][0] *= a0;
                oacc[mi][ni][1] *= a0;
                oacc[mi][ni][2] *= a1;
                oacc[mi][ni][3] *= a1;
            }
        }
#pragma unroll
        for (int kk = 0; kk < 64; kk += 8) {
            uint32_t af[2][4], bf[4][2];
#pragma unroll
            for (int mi = 0; mi < 2; mi++) {
                const int m0 = wmq + mi * 16 + grp;
                af[mi][0] = __float_as_uint(Ss[m0 * SP + kk + tig]);
                af[mi][1] = __float_as_uint(Ss[(m0 + 8) * SP + kk + tig]);
                af[mi][2] = __float_as_uint(Ss[m0 * SP + kk + tig + 4]);
                af[mi][3] = __float_as_uint(Ss[(m0 + 8) * SP + kk + tig + 4]);
            }
#pragma unroll
            for (int ni = 0; ni < 4; ni++) {
                const int n0 = wn + ni * 8 + grp;       // d index
                bf[ni][0] = __float_as_uint(Vs[(kk + tig) * VP + n0]);
                bf[ni][1] = __float_as_uint(Vs[(kk + tig + 4) * VP + n0]);
            }
#pragma unroll
            for (int mi = 0; mi < 2; mi++)
#pragma unroll
                for (int ni = 0; ni < 4; ni++)
                    MMA_TF32(oacc[mi][ni], af[mi], bf[ni]);
        }
        __syncthreads();
    }

    // epilogue: normalize and write
    float* obase = out + ((size_t)(b * TQ + qt * 128)) * DIMC + h * HD;
#pragma unroll
    for (int mi = 0; mi < 2; mi++) {
        const int r0 = wmq + mi * 16 + grp;
        const float inv0 = 1.0f / sm_l[r0];
        const float inv1 = 1.0f / sm_l[r0 + 8];
#pragma unroll
        for (int ni = 0; ni < 4; ni++) {
            const int col = wn + ni * 8 + tig * 2;
            *(float2*)(obase + (size_t)r0 * DIMC + col) =
                make_float2(oacc[mi][ni][0] * inv0, oacc[mi][ni][1] * inv0);
            *(float2*)(obase + (size_t)(r0 + 8) * DIMC + col) =
                make_float2(oacc[mi][ni][2] * inv1, oacc[mi][ni][3] * inv1);
        }
    }
}

// ---------------- LayerNorm over C=1024, one block per row ----------------
__global__ __launch_bounds__(256)
void ln_kernel(const float* __restrict__ Y, const float* __restrict__ g,
               const float* __restrict__ bb, float* __restrict__ O)
{
    const int row = blockIdx.x;
    const int tid = threadIdx.x;
    const int c = tid * 4;
    float4 v = *(const float4*)(Y + (size_t)row * DIMC + c);
    float s  = v.x + v.y + v.z + v.w;
    float sq = v.x * v.x + v.y * v.y + v.z * v.z + v.w * v.w;
#pragma unroll
    for (int off = 16; off; off >>= 1) {
        s  += __shfl_xor_sync(0xffffffffu, s, off);
        sq += __shfl_xor_sync(0xffffffffu, sq, off);
    }
    __shared__ float ws[8], wsq[8];
    __shared__ float sh_mu, sh_r;
    const int w = tid >> 5, l = tid & 31;
    if (l == 0) { ws[w] = s; wsq[w] = sq; }
    __syncthreads();
    if (tid == 0) {
        float S = 0.0f, Q = 0.0f;
#pragma unroll
        for (int i = 0; i < 8; i++) { S += ws[i]; Q += wsq[i]; }
        float mu  = S / (float)DIMC;
        float var = Q / (float)DIMC - mu * mu;
        sh_mu = mu;
        sh_r  = rsqrtf(var + 1e-5f);
    }
    __syncthreads();
    const float mu = sh_mu, r = sh_r;
    float4 gg = *(const float4*)(g + c);
    float4 b4 = *(const float4*)(bb + c);
    float4 o4;
    o4.x = (v.x - mu) * r * gg.x + b4.x;
    o4.y = (v.y - mu) * r * gg.y + b4.y;
    o4.z = (v.z - mu) * r * gg.z + b4.z;
    o4.w = (v.w - mu) * r * gg.w + b4.w;
    *(float4*)(O + (size_t)row * DIMC + c) = o4;
}

// ---------------- launcher ----------------
extern "C" void kernel_launch(void* const* d_in, const int* in_sizes, int n_in,
                              void* d_out, int out_size)
{
    const float* x    = (const float*)d_in[0];
    const float* h_t  = (const float*)d_in[1];
    const float* h_a  = (const float*)d_in[2];
    const float* p    = (const float*)d_in[3];
    const float* wq   = (const float*)d_in[4];  const float* bq  = (const float*)d_in[5];
    const float* wks  = (const float*)d_in[6];  const float* bks = (const float*)d_in[7];
    const float* wvs  = (const float*)d_in[8];  const float* bvs = (const float*)d_in[9];
    const float* wka  = (const float*)d_in[10]; const float* bka = (const float*)d_in[11];
    const float* wva  = (const float*)d_in[12]; const float* bva = (const float*)d_in[13];
    const float* wkt  = (const float*)d_in[14]; const float* bkt = (const float*)d_in[15];
    const float* wvt  = (const float*)d_in[16]; const float* bvt = (const float*)d_in[17];
    const float* wo   = (const float*)d_in[18]; const float* bo  = (const float*)d_in[19];
    const float* wf   = (const float*)d_in[20]; const float* bf  = (const float*)d_in[21];
    const float* ln_g = (const float*)d_in[22];
    const float* ln_b = (const float*)d_in[23];
    const float* gate = (const float*)d_in[24];
    float* out = (float*)d_out;

    float *q_, *ktok_, *vtok_, *had_, *kada_, *vada_, *ktsk_, *vtsk_, *attn_, *y_, *yln_;
    cudaGetSymbolAddress((void**)&q_,    g_q);
    cudaGetSymbolAddress((void**)&ktok_, g_ktok);
    cudaGetSymbolAddress((void**)&vtok_, g_vtok);
    cudaGetSymbolAddress((void**)&had_,  g_had);
    cudaGetSymbolAddress((void**)&kada_, g_kada);
    cudaGetSymbolAddress((void**)&vada_, g_vada);
    cudaGetSymbolAddress((void**)&ktsk_, g_ktsk);
    cudaGetSymbolAddress((void**)&vtsk_, g_vtsk);
    cudaGetSymbolAddress((void**)&attn_, g_attn);
    cudaGetSymbolAddress((void**)&y_,    g_y);
    cudaGetSymbolAddress((void**)&yln_,  g_yln);

    const int ATTN_SMEM = (128 * QP + 64 * KP + 64 * VP + 128 * SP + 3 * 128 + 256) * 4; // 108032 B
    cudaFuncSetAttribute(attn_tc_kernel, cudaFuncAttributeMaxDynamicSharedMemorySize, ATTN_SMEM);

    dim3 blk(256);

    // h_adapter = concat(h_a, p)
    concat_kernel<<<(NADROWS * DIMC / 4 + 255) / 256, 256>>>(h_a, p, had_);

    dim3 gx(8, 32, 3);    // x projections: wq, wks, wvs
    dim3 gad(8, 10, 2);   // adapter: wka, wva
    dim3 gtk(8, 16, 2);   // task: wkt, wvt
    dim3 g1(8, 32);

    gemm3_tf32_kernel<<<gx, blk>>>(x, wq, wks, wvs, bq, bks, bvs,
                                   q_, ktok_, vtok_, DIMC, DIMC, TQ, TQ, 0);
    gemm3_tf32_kernel<<<gad, blk>>>(had_, wka, wva, nullptr, bka, bva, nullptr,
                                    kada_, vada_, nullptr, DIMC, DIMC, KADA, 0, 0);
    gemm3_tf32_kernel<<<gtk, blk>>>(h_t, wkt, wvt, nullptr, bkt, bvt, nullptr,
                                    ktsk_, vtsk_, nullptr, DIMC, DIMC, KTSK, 0, 0);

    dim3 ga(TQ / 128, HEADS, BATCH);   // (8, 16, 4)
    attn_tc_kernel<<<ga, 256, ATTN_SMEM>>>(q_, ktok_, vtok_, kada_, vada_, ktsk_, vtsk_, gate, attn_);

    gemm_tf32_kernel<<<g1, blk>>>(attn_, wo, bo, x, y_, DIMC, DIMC, 0, 0);
    ln_kernel<<<NQROWS, 256>>>(y_, ln_g, ln_b, yln_);
    gemm_tf32_kernel<<<g1, blk>>>(yln_, wf, bf, nullptr, out, DIMC, DIMC, 0, 1);
}

// round 14
// speedup vs baseline: 3.4883x; 1.1912x over previous
#include <cuda_runtime.h>
#include <math.h>
#include <stdint.h>

#define DIMC    1024
#define BATCH   4
#define TQ      1024
#define HEADS   16
#define HD      64
#define KADA    320
#define KTSK    512
#define NQROWS  (BATCH*TQ)     /* 4096 */
#define NADROWS (BATCH*KADA)   /* 1280 */
#define NTKROWS (BATCH*KTSK)   /* 2048 */
#define NTILES  29             /* 16 tok + 5 ada + 8 tsk, 64 keys each = 1856 */

// ---------------- scratch (device globals; no runtime allocation) ----------------
__device__ float g_q   [NQROWS * DIMC];
__device__ float g_ktok[NQROWS * DIMC];
__device__ float g_vtok[NQROWS * DIMC];
__device__ float g_had [NADROWS * DIMC];
__device__ float g_kada[NADROWS * DIMC];
__device__ float g_vada[NADROWS * DIMC];
__device__ float g_ktsk[NTKROWS * DIMC];
__device__ float g_vtsk[NTKROWS * DIMC];
__device__ float g_attn[NQROWS * DIMC];
__device__ float g_y   [NQROWS * DIMC];
__device__ float g_yln [NQROWS * DIMC];
__device__ float g_xr  [NQROWS * DIMC];        // tf32-rounded x
__device__ float g_htr [NTKROWS * DIMC];       // tf32-rounded h_t
__device__ float g_wr  [9][DIMC * DIMC];       // tf32-rounded weights

// ---------------- tf32 helpers ----------------
__device__ __forceinline__ float tf32r(float x) {
    uint32_t u;
    asm("cvt.rna.tf32.f32 %0, %1;" : "=r"(u) : "f"(x));
    return __uint_as_float(u);
}
__device__ __forceinline__ float4 tf32r4(float4 v) {
    return make_float4(tf32r(v.x), tf32r(v.y), tf32r(v.z), tf32r(v.w));
}

#define MMA_TF32(acc, a, b)                                                    \
    asm volatile(                                                              \
        "mma.sync.aligned.m16n8k8.row.col.f32.tf32.tf32.f32 "                  \
        "{%0,%1,%2,%3}, {%4,%5,%6,%7}, {%8,%9}, {%0,%1,%2,%3};\n"              \
        : "+f"((acc)[0]), "+f"((acc)[1]), "+f"((acc)[2]), "+f"((acc)[3])       \
        : "r"((a)[0]), "r"((a)[1]), "r"((a)[2]), "r"((a)[3]),                  \
          "r"((b)[0]), "r"((b)[1]))

__device__ __forceinline__ void cpa16(uint32_t dst, const float* src) {
    asm volatile("cp.async.cg.shared.global [%0], [%1], 16;\n"
                 :: "r"(dst), "l"(src));
}

// ---------------- pre-round pass: x, h_t, 9 weights -> tf32 ----------------
struct RoundArgs { const float* src[11]; float* dst[11]; };
__global__ __launch_bounds__(256)
void round_all(RoundArgs ra)
{
    int idx = blockIdx.x * 256 + threadIdx.x;    // float4 index
    int seg, off;
    if (idx < 1048576)      { seg = 0; off = idx; }                 // x: 4M floats
    else if (idx < 1572864) { seg = 1; off = idx - 1048576; }       // h_t: 2M
    else {
        int r = idx - 1572864;                                      // 9 x 1M
        seg = 2 + (r >> 18);
        off = r & 262143;
    }
    const float4* s = (const float4*)ra.src[seg];
    float4* d = (float4*)ra.dst[seg];
    d[off] = tf32r4(s[off]);
}

// ---------------- h_adapter = concat(h_a, p), tf32-rounded ----------------
__global__ void concat_kernel(const float* __restrict__ ha,
                              const float* __restrict__ pp,
                              float* __restrict__ out)
{
    int idx = blockIdx.x * blockDim.x + threadIdx.x;     // float4 index
    const int C4 = DIMC / 4;
    const int total = NADROWS * C4;
    if (idx >= total) return;
    int c4  = idx % C4;
    int row = idx / C4;
    int b = row / KADA;
    int s = row % KADA;
    float4 v;
    if (s < 256) v = ((const float4*)ha)[(size_t)(b * 256 + s) * C4 + c4];
    else         v = ((const float4*)pp)[(size_t)(b * 64 + (s - 256)) * C4 + c4];
    ((float4*)out)[idx] = tf32r4(v);
}

// ---------------- TF32 GEMM core: cp.async 3-stage pipeline ----------------
// C[.x128 tiles] = A[Mx1024(tf32)] @ W[1024x1024(tf32)] + bias (+res fp32)
// 128x128 CTA tile, BK=16, 8 warps 2(m)x4(n), warp tile 64x32 m16n8k8.
// A smem [m][k] pitch 20 (frag banks grp*20+tig: conflict-free);
// B smem [k][n] pitch 136 (frag banks tig*8+grp: conflict-free).
#define APITCH 20
#define BPITCH 136
#define A_STG  (128 * APITCH)   /* 2560 floats */
#define B_STG  (16 * BPITCH)    /* 2176 floats */
#define NSTG   3
#define GEMM_SMEM (NSTG * (A_STG + B_STG) * 4)   /* 56832 B */

__device__ __forceinline__ void gemm_body(
    const float* __restrict__ A, const float* __restrict__ W,
    const float* __restrict__ bias, const float* __restrict__ res,
    float* __restrict__ C, int K, int N, int rope_seq, int do_relu,
    int bm, int bn, int round_out, float* smem)
{
    float* smA = smem;
    float* smB = smem + NSTG * A_STG;

    const int tid  = threadIdx.x;
    const int lane = tid & 31, warp = tid >> 5;
    const int grp  = lane >> 2, tig = lane & 3;
    const int wm   = (warp >> 2) * 64;
    const int wn   = (warp & 3) * 32;

    // cp.async mapping: A rows tid>>2 (+64), 16B chunk (tid&3); B row tid>>5 (+8), 16B col
    const int arow0 = tid >> 2, ach = tid & 3;
    const int bk0   = tid >> 5;
    const int bn0   = (tid & 31) << 2;
    const float* Asrc0 = A + (size_t)(bm + arow0) * K + ach * 4;
    const float* Asrc1 = Asrc0 + (size_t)64 * K;
    const float* Bsrc0 = W + (size_t)bk0 * N + bn + bn0;
    const float* Bsrc1 = Bsrc0 + (size_t)8 * N;
    const uint32_t AdstBase = (uint32_t)__cvta_generic_to_shared(smA) + (arow0 * APITCH + ach * 4) * 4;
    const uint32_t BdstBase = (uint32_t)__cvta_generic_to_shared(smB) + (bk0 * BPITCH + bn0) * 4;
    const uint32_t Ad1 = 64 * APITCH * 4;
    const uint32_t Bd1 = 8 * BPITCH * 4;

#define G_ISSUE(sb, kk0) do {                                                  \
        uint32_t _ao = (uint32_t)(sb) * (A_STG * 4);                           \
        uint32_t _bo = (uint32_t)(sb) * (B_STG * 4);                           \
        cpa16(AdstBase + _ao,       Asrc0 + (kk0));                            \
        cpa16(AdstBase + _ao + Ad1, Asrc1 + (kk0));                            \
        cpa16(BdstBase + _bo,       Bsrc0 + (size_t)(kk0) * N);                \
        cpa16(BdstBase + _bo + Bd1, Bsrc1 + (size_t)(kk0) * N);                \
        asm volatile("cp.async.commit_group;\n" ::: "memory");                 \
    } while (0)

    float acc[4][4][4];
#pragma unroll
    for (int i = 0; i < 4; i++)
#pragma unroll
        for (int j = 0; j < 4; j++)
#pragma unroll
            for (int r = 0; r < 4; r++) acc[i][j][r] = 0.0f;

    const int NSLAB = K >> 4;
    G_ISSUE(0, 0);
    G_ISSUE(1, 16);

    int buf = 0;
    for (int i = 0; i < NSLAB; i++) {
        if (i == NSLAB - 1) asm volatile("cp.async.wait_group 0;\n" ::: "memory");
        else                asm volatile("cp.async.wait_group 1;\n" ::: "memory");
        __syncthreads();

        if (i + 2 < NSLAB) {
            int nbuf = buf + 2; if (nbuf >= 3) nbuf -= 3;
            G_ISSUE(nbuf, (i + 2) * 16);
        }

        const float* As = smA + buf * A_STG;
        const float* Bs = smB + buf * B_STG;
#pragma unroll
        for (int kk = 0; kk < 16; kk += 8) {
            uint32_t af[4][4], bf[4][2];
#pragma unroll
            for (int mi = 0; mi < 4; mi++) {
                const int m0 = wm + mi * 16 + grp;
                af[mi][0] = __float_as_uint(As[m0 * APITCH + kk + tig]);
                af[mi][1] = __float_as_uint(As[(m0 + 8) * APITCH + kk + tig]);
                af[mi][2] = __float_as_uint(As[m0 * APITCH + kk + tig + 4]);
                af[mi][3] = __float_as_uint(As[(m0 + 8) * APITCH + kk + tig + 4]);
            }
#pragma unroll
            for (int ni = 0; ni < 4; ni++) {
                const int n0 = wn + ni * 8 + grp;
                bf[ni][0] = __float_as_uint(Bs[(kk + tig) * BPITCH + n0]);
                bf[ni][1] = __float_as_uint(Bs[(kk + tig + 4) * BPITCH + n0]);
            }
#pragma unroll
            for (int mi = 0; mi < 4; mi++)
#pragma unroll
                for (int ni = 0; ni < 4; ni++)
                    MMA_TF32(acc[mi][ni], af[mi], bf[ni]);
        }
        buf++; if (buf == 3) buf = 0;
    }
#undef G_ISSUE

    // epilogue: thread owns col pairs (even, even+1) -> rope pairs align.
#pragma unroll
    for (int mi = 0; mi < 4; mi++) {
#pragma unroll
        for (int half = 0; half < 2; half++) {
            const int gRow = bm + wm + mi * 16 + grp + half * 8;
            const int pos = rope_seq ? (gRow % rope_seq) : 0;
            const float fp = (float)pos;
#pragma unroll
            for (int ni = 0; ni < 4; ni++) {
                const int gCol = bn + wn + ni * 8 + tig * 2;
                float v0 = acc[mi][ni][half * 2 + 0] + bias[gCol];
                float v1 = acc[mi][ni][half * 2 + 1] + bias[gCol + 1];
                if (res) {
                    const float* rr = res + (size_t)gRow * N + gCol;
                    v0 += rr[0];
                    v1 += rr[1];
                }
                if (rope_seq) {
                    const int d  = gCol & 63;       // even
                    const int f0 = d & 31;          // concat tables: freq idx = d % 32
                    float inv0 = exp2f((float)f0       * -0.41524101186409203f);
                    float inv1 = exp2f((float)(f0 + 1) * -0.41524101186409203f);
                    float s0, c0, s1, c1;
                    sincosf(fp * inv0, &s0, &c0);
                    sincosf(fp * inv1, &s1, &c1);
                    float e = v0, o = v1;
                    v0 = e * c0 - o * s0;
                    v1 = o * c1 + e * s1;
                }
                if (do_relu) {
                    v0 = fmaxf(v0, 0.0f);
                    v1 = fmaxf(v1, 0.0f);
                }
                if (round_out) { v0 = tf32r(v0); v1 = tf32r(v1); }
                *(float2*)(C + (size_t)gRow * N + gCol) = make_float2(v0, v1);
            }
        }
    }
}

__global__ __launch_bounds__(256, 2)
void gemm_tf32_kernel(const float* __restrict__ A, const float* __restrict__ W,
                      const float* __restrict__ bias, const float* __restrict__ res,
                      float* __restrict__ C, int rope_seq, int do_relu)
{
    extern __shared__ float dynsm[];
    gemm_body(A, W, bias, res, C, DIMC, DIMC, rope_seq, do_relu,
              blockIdx.y * 128, blockIdx.x * 128, 0, dynsm);
}

// all 7 projection GEMMs in one launch; epilogue writes tf32-rounded outputs
struct G7 {
    const float* A[7]; const float* W[7]; const float* bias[7];
    float* C[7]; int rope[7]; int base[7];
};
__global__ __launch_bounds__(256, 2)
void gemm7_kernel(G7 g)
{
    extern __shared__ float dynsm[];
    const int bid = blockIdx.x;
    int seg = 0;
#pragma unroll
    for (int s = 1; s < 7; s++)
        if (bid >= g.base[s]) seg = s;
    const int loc = bid - g.base[seg];
    gemm_body(g.A[seg], g.W[seg], g.bias[seg], nullptr, g.C[seg],
              DIMC, DIMC, g.rope[seg], 0, (loc >> 3) * 128, (loc & 7) * 128,
              1, dynsm);
}

// ---------------- tensor-core flash attention ----------------
// Inputs are pre-rounded tf32 (gemm7 epilogue). Output tf32-rounded (feeds wo GEMM).
#define QP 68
#define KP 68
#define VP 72
#define SP 68
#define ATTN_SMEM_F (128 * QP + 64 * KP + 64 * VP + 128 * SP + 3 * 128)
__global__ __launch_bounds__(256, 2)
void attn_tc_kernel(const float* __restrict__ q,
                    const float* __restrict__ ktok, const float* __restrict__ vtok,
                    const float* __restrict__ kada, const float* __restrict__ vada,
                    const float* __restrict__ ktsk, const float* __restrict__ vtsk,
                    const float* __restrict__ gate, float* __restrict__ out)
{
    extern __shared__ float sm[];
    float* Qs   = sm;                 // [q][d]    128 x QP
    float* Ks   = Qs + 128 * QP;      // [key][d]  64 x KP
    float* Vs   = Ks + 64 * KP;       // [key][d]  64 x VP
    float* Ss   = Vs + 64 * VP;       // [q][key]  128 x SP
    float* sm_m = Ss + 128 * SP;      // 128
    float* sm_l = sm_m + 128;         // 128
    float* sm_a = sm_l + 128;         // 128

    const int b = blockIdx.z, h = blockIdx.y, qt = blockIdx.x;
    const int tid  = threadIdx.x;
    const int lane = tid & 31, warp = tid >> 5;
    const int grp  = lane >> 2, tig = lane & 3;
    const int wmq  = (warp >> 1) * 32;   // q offset: 0,32,64,96
    const int wn   = (warp & 1) * 32;    // key/d offset: 0,32
    const float gfac = tanhf(gate[0]);

    const float* qbase = q + ((size_t)(b * TQ + qt * 128)) * DIMC + h * HD;
    for (int f = tid; f < 2048; f += 256) {
        int r = f >> 4, d4 = (f & 15) << 2;
        *(float4*)&Qs[r * QP + d4] = *(const float4*)(qbase + (size_t)r * DIMC + d4);
    }
    if (tid < 128) { sm_m[tid] = -1e30f; sm_l[tid] = 0.0f; }

    float oacc[2][4][4];
#pragma unroll
    for (int i = 0; i < 2; i++)
#pragma unroll
        for (int j = 0; j < 4; j++)
#pragma unroll
            for (int r = 0; r < 4; r++) oacc[i][j][r] = 0.0f;
    __syncthreads();

    for (int kt = 0; kt < NTILES; kt++) {
        const float *kp, *vp;
        float sscale;
        if (kt < 16) {
            size_t off = ((size_t)(b * TQ + kt * 64)) * DIMC + h * HD;
            kp = ktok + off; vp = vtok + off; sscale = 0.125f;
        } else if (kt < 21) {
            size_t off = ((size_t)(b * KADA + (kt - 16) * 64)) * DIMC + h * HD;
            kp = kada + off; vp = vada + off; sscale = 0.125f;
        } else {
            size_t off = ((size_t)(b * KTSK + (kt - 21) * 64)) * DIMC + h * HD;
            kp = ktsk + off; vp = vtsk + off; sscale = 0.125f * gfac;
        }

        for (int f = tid; f < 1024; f += 256) {
            int r = f >> 4, d4 = (f & 15) << 2;
            *(float4*)&Ks[r * KP + d4] = *(const float4*)(kp + (size_t)r * DIMC + d4);
            *(float4*)&Vs[r * VP + d4] = *(const float4*)(vp + (size_t)r * DIMC + d4);
        }
        __syncthreads();

        // ---- S = Q · K^T ----
        float sacc[2][4][4];
#pragma unroll
        for (int i = 0; i < 2; i++)
#pragma unroll
            for (int j = 0; j < 4; j++)
#pragma unroll
                for (int r = 0; r < 4; r++) sacc[i][j][r] = 0.0f;

#pragma unroll
        for (int kk = 0; kk < 64; kk += 8) {
            uint32_t af[2][4], bf[4][2];
#pragma unroll
            for (int mi = 0; mi < 2; mi++) {
                const int m0 = wmq + mi * 16 + grp;
                af[mi][0] = __float_as_uint(Qs[m0 * QP + kk + tig]);
                af[mi][1] = __float_as_uint(Qs[(m0 + 8) * QP + kk + tig]);
                af[mi][2] = __float_as_uint(Qs[m0 * QP + kk + tig + 4]);
                af[mi][3] = __float_as_uint(Qs[(m0 + 8) * QP + kk + tig + 4]);
            }
#pragma unroll
            for (int ni = 0; ni < 4; ni++) {
                const int n0 = wn + ni * 8 + grp;
                bf[ni][0] = __float_as_uint(Ks[n0 * KP + kk + tig]);
                bf[ni][1] = __float_as_uint(Ks[n0 * KP + kk + tig + 4]);
            }
#pragma unroll
            for (int mi = 0; mi < 2; mi++)
#pragma unroll
                for (int ni = 0; ni < 4; ni++)
                    MMA_TF32(sacc[mi][ni], af[mi], bf[ni]);
        }
#pragma unroll
        for (int mi = 0; mi < 2; mi++) {
            const int r0 = wmq + mi * 16 + grp;
#pragma unroll
            for (int ni = 0; ni < 4; ni++) {
                const int col = wn + ni * 8 + tig * 2;
                *(float2*)&Ss[r0 * SP + col] =
                    make_float2(sacc[mi][ni][0] * sscale, sacc[mi][ni][1] * sscale);
                *(float2*)&Ss[(r0 + 8) * SP + col] =
                    make_float2(sacc[mi][ni][2] * sscale, sacc[mi][ni][3] * sscale);
            }
        }
        __syncthreads();

        // ---- online softmax (pair of lanes per q row; shuffle reductions) ----
        const int qc = tid >> 1, part = tid & 1;
        float* srow = &Ss[qc * SP + part * 32];
        float lm = -1e30f;
#pragma unroll
        for (int k = 0; k < 32; k++) lm = fmaxf(lm, srow[k]);
        lm = fmaxf(lm, __shfl_xor_sync(0xffffffffu, lm, 1));
        const float mold = sm_m[qc];
        const float mn = fmaxf(mold, lm);
        const float alpha = __expf(mold - mn);
        float lsum = 0.0f;
#pragma unroll
        for (int k = 0; k < 32; k++) {
            float pv = tf32r(__expf(srow[k] - mn));
            srow[k] = pv;
            lsum += pv;
        }
        lsum += __shfl_xor_sync(0xffffffffu, lsum, 1);
        if (part == 0) {
            sm_m[qc] = mn;
            sm_a[qc] = alpha;
            sm_l[qc] = sm_l[qc] * alpha + lsum;
        }
        __syncthreads();

        // ---- O = O*alpha + P · V ----
#pragma unroll
        for (int mi = 0; mi < 2; mi++) {
            const float a0 = sm_a[wmq + mi * 16 + grp];
            const float a1 = sm_a[wmq + mi * 16 + grp + 8];
#pragma unroll
            for (int ni = 0; ni < 4; ni++) {
                oacc[mi][ni][0] *= a0;
                oacc[mi][ni][1] *= a0;
                oacc[mi][ni][2] *= a1;
                oacc[mi][ni][3] *= a1;
            }
        }
#pragma unroll
        for (int kk = 0; kk < 64; kk += 8) {
            uint32_t af[2][4], bf[4][2];
#pragma unroll
            for (int mi = 0; mi < 2; mi++) {
                const int m0 = wmq + mi * 16 + grp;
                af[mi][0] = __float_as_uint(Ss[m0 * SP + kk + tig]);
                af[mi][1] = __float_as_uint(Ss[(m0 + 8) * SP + kk + tig]);
                af[mi][2] = __float_as_uint(Ss[m0 * SP + kk + tig + 4]);
                af[mi][3] = __float_as_uint(Ss[(m0 + 8) * SP + kk + tig + 4]);
            }
#pragma unroll
            for (int ni = 0; ni < 4; ni++) {
                const int n0 = wn + ni * 8 + grp;
                bf[ni][0] = __float_as_uint(Vs[(kk + tig) * VP + n0]);
                bf[ni][1] = __float_as_uint(Vs[(kk + tig + 4) * VP + n0]);
            }
#pragma unroll
            for (int mi = 0; mi < 2; mi++)
#pragma unroll
                for (int ni = 0; ni < 4; ni++)
                    MMA_TF32(oacc[mi][ni], af[mi], bf[ni]);
        }
        __syncthreads();
    }

    // epilogue: normalize, round (feeds wo GEMM), write
    float* obase = out + ((size_t)(b * TQ + qt * 128)) * DIMC + h * HD;
#pragma unroll
    for (int mi = 0; mi < 2; mi++) {
        const int r0 = wmq + mi * 16 + grp;
        const float inv0 = 1.0f / sm_l[r0];
        const float inv1 = 1.0f / sm_l[r0 + 8];
#pragma unroll
        for (int ni = 0; ni < 4; ni++) {
            const int col = wn + ni * 8 + tig * 2;
            *(float2*)(obase + (size_t)r0 * DIMC + col) =
                make_float2(tf32r(oacc[mi][ni][0] * inv0), tf32r(oacc[mi][ni][1] * inv0));
            *(float2*)(obase + (size_t)(r0 + 8) * DIMC + col) =
                make_float2(tf32r(oacc[mi][ni][2] * inv1), tf32r(oacc[mi][ni][3] * inv1));
        }
    }
}

// ---------------- LayerNorm (output tf32-rounded; feeds wf GEMM) ----------------
__global__ __launch_bounds__(256)
void ln_kernel(const float* __restrict__ Y, const float* __restrict__ g,
               const float* __restrict__ bb, float* __restrict__ O)
{
    const int row = blockIdx.x;
    const int tid = threadIdx.x;
    const int c = tid * 4;
    float4 v = *(const float4*)(Y + (size_t)row * DIMC + c);
    float s  = v.x + v.y + v.z + v.w;
    float sq = v.x * v.x + v.y * v.y + v.z * v.z + v.w * v.w;
#pragma unroll
    for (int off = 16; off; off >>= 1) {
        s  += __shfl_xor_sync(0xffffffffu, s, off);
        sq += __shfl_xor_sync(0xffffffffu, sq, off);
    }
    __shared__ float ws[8], wsq[8];
    __shared__ float sh_mu, sh_r;
    const int w = tid >> 5, l = tid & 31;
    if (l == 0) { ws[w] = s; wsq[w] = sq; }
    __syncthreads();
    if (tid == 0) {
        float S = 0.0f, Q = 0.0f;
#pragma unroll
        for (int i = 0; i < 8; i++) { S += ws[i]; Q += wsq[i]; }
        float mu  = S / (float)DIMC;
        float var = Q / (float)DIMC - mu * mu;
        sh_mu = mu;
        sh_r  = rsqrtf(var + 1e-5f);
    }
    __syncthreads();
    const float mu = sh_mu, r = sh_r;
    float4 gg = *(const float4*)(g + c);
    float4 b4 = *(const float4*)(bb + c);
    float4 o4;
    o4.x = tf32r((v.x - mu) * r * gg.x + b4.x);
    o4.y = tf32r((v.y - mu) * r * gg.y + b4.y);
    o4.z = tf32r((v.z - mu) * r * gg.z + b4.z);
    o4.w = tf32r((v.w - mu) * r * gg.w + b4.w);
    *(float4*)(O + (size_t)row * DIMC + c) = o4;
}

// ---------------- launcher ----------------
extern "C" void kernel_launch(void* const* d_in, const int* in_sizes, int n_in,
                              void* d_out, int out_size)
{
    const float* x    = (const float*)d_in[0];
    const float* h_t  = (const float*)d_in[1];
    const float* h_a  = (const float*)d_in[2];
    const float* p    = (const float*)d_in[3];
    const float* wq   = (const float*)d_in[4];  const float* bq  = (const float*)d_in[5];
    const float* wks  = (const float*)d_in[6];  const float* bks = (const float*)d_in[7];
    const float* wvs  = (const float*)d_in[8];  const float* bvs = (const float*)d_in[9];
    const float* wka  = (const float*)d_in[10]; const float* bka = (const float*)d_in[11];
    const float* wva  = (const float*)d_in[12]; const float* bva = (const float*)d_in[13];
    const float* wkt  = (const float*)d_in[14]; const float* bkt = (const float*)d_in[15];
    const float* wvt  = (const float*)d_in[16]; const float* bvt = (const float*)d_in[17];
    const float* wo   = (const float*)d_in[18]; const float* bo  = (const float*)d_in[19];
    const float* wf   = (const float*)d_in[20]; const float* bf  = (const float*)d_in[21];
    const float* ln_g = (const float*)d_in[22];
    const float* ln_b = (const float*)d_in[23];
    const float* gate = (const float*)d_in[24];
    float* out = (float*)d_out;

    float *q_, *ktok_, *vtok_, *had_, *kada_, *vada_, *ktsk_, *vtsk_, *attn_, *y_, *yln_;
    float *xr_, *htr_, *wr_;
    cudaGetSymbolAddress((void**)&q_,    g_q);
    cudaGetSymbolAddress((void**)&ktok_, g_ktok);
    cudaGetSymbolAddress((void**)&vtok_, g_vtok);
    cudaGetSymbolAddress((void**)&had_,  g_had);
    cudaGetSymbolAddress((void**)&kada_, g_kada);
    cudaGetSymbolAddress((void**)&vada_, g_vada);
    cudaGetSymbolAddress((void**)&ktsk_, g_ktsk);
    cudaGetSymbolAddress((void**)&vtsk_, g_vtsk);
    cudaGetSymbolAddress((void**)&attn_, g_attn);
    cudaGetSymbolAddress((void**)&y_,    g_y);
    cudaGetSymbolAddress((void**)&yln_,  g_yln);
    cudaGetSymbolAddress((void**)&xr_,   g_xr);
    cudaGetSymbolAddress((void**)&htr_,  g_htr);
    cudaGetSymbolAddress((void**)&wr_,   g_wr);

    float* wrp[9];
    for (int i = 0; i < 9; i++) wrp[i] = wr_ + (size_t)i * DIMC * DIMC;

    const int ATTN_SMEM = ATTN_SMEM_F * 4;
    cudaFuncSetAttribute(attn_tc_kernel, cudaFuncAttributeMaxDynamicSharedMemorySize, ATTN_SMEM);
    cudaFuncSetAttribute(gemm_tf32_kernel, cudaFuncAttributeMaxDynamicSharedMemorySize, GEMM_SMEM);
    cudaFuncSetAttribute(gemm7_kernel, cudaFuncAttributeMaxDynamicSharedMemorySize, GEMM_SMEM);

    // 1. pre-round x, h_t, 9 weights
    RoundArgs ra;
    ra.src[0] = x;    ra.dst[0] = xr_;
    ra.src[1] = h_t;  ra.dst[1] = htr_;
    const float* wsrc[9] = {wq, wks, wvs, wka, wva, wkt, wvt, wo, wf};
    for (int i = 0; i < 9; i++) { ra.src[2 + i] = wsrc[i]; ra.dst[2 + i] = wrp[i]; }
    round_all<<<15360, 256>>>(ra);

    // 2. h_adapter = concat(h_a, p) (rounded)
    concat_kernel<<<(NADROWS * DIMC / 4 + 255) / 256, 256>>>(h_a, p, had_);

    // 3. all 7 projections in one launch (outputs rounded post-rope)
    G7 g7;
    const float* As[7]   = {xr_, xr_, xr_, had_, had_, htr_, htr_};
    const float* Ws[7]   = {wrp[0], wrp[1], wrp[2], wrp[3], wrp[4], wrp[5], wrp[6]};
    const float* Bi[7]   = {bq, bks, bvs, bka, bva, bkt, bvt};
    float* Cs[7]         = {q_, ktok_, vtok_, kada_, vada_, ktsk_, vtsk_};
    const int ropes[7]   = {TQ, TQ, 0, KADA, 0, KTSK, 0};
    const int bases[7]   = {0, 256, 512, 768, 848, 928, 1056};
    for (int i = 0; i < 7; i++) {
        g7.A[i] = As[i]; g7.W[i] = Ws[i]; g7.bias[i] = Bi[i];
        g7.C[i] = Cs[i]; g7.rope[i] = ropes[i]; g7.base[i] = bases[i];
    }
    gemm7_kernel<<<1184, 256, GEMM_SMEM>>>(g7);

    // 4. attention (inputs pre-rounded; output rounded)
    dim3 ga(TQ / 128, HEADS, BATCH);
    attn_tc_kernel<<<ga, 256, ATTN_SMEM>>>(q_, ktok_, vtok_, kada_, vada_, ktsk_, vtsk_, gate, attn_);

    // 5. wo GEMM + residual (res = original fp32 x)
    dim3 g1(8, 32);
    gemm_tf32_kernel<<<g1, 256, GEMM_SMEM>>>(attn_, wrp[7], bo, x, y_, 0, 0);

    // 6. LayerNorm (output rounded)
    ln_kernel<<<NQROWS, 256>>>(y_, ln_g, ln_b, yln_);

    // 7. wf GEMM + ReLU -> out
    gemm_tf32_kernel<<<g1, 256, GEMM_SMEM>>>(yln_, wrp[8], bf, nullptr, out, 0, 1);
}

// round 17
// speedup vs baseline: 3.6167x; 1.0368x over previous
#include <cuda_runtime.h>
#include <math.h>
#include <stdint.h>

#define DIMC    1024
#define BATCH   4
#define TQ      1024
#define HEADS   16
#define HD      64
#define KADA    320
#define KTSK    512
#define NQROWS  (BATCH*TQ)     /* 4096 */
#define NADROWS (BATCH*KADA)   /* 1280 */
#define NTKROWS (BATCH*KTSK)   /* 2048 */
#define NTILES  29             /* 16 tok + 5 ada + 8 tsk, 64 keys each = 1856 */

// ---------------- scratch (device globals; no runtime allocation) ----------------
__device__ float g_q   [NQROWS * DIMC];
__device__ float g_ktok[NQROWS * DIMC];
__device__ float g_vtok[NQROWS * DIMC];
__device__ float g_had [NADROWS * DIMC];
__device__ float g_kada[NADROWS * DIMC];
__device__ float g_vada[NADROWS * DIMC];
__device__ float g_ktsk[NTKROWS * DIMC];
__device__ float g_vtsk[NTKROWS * DIMC];
__device__ float g_attn[NQROWS * DIMC];
__device__ float g_y   [NQROWS * DIMC];
__device__ float g_yln [NQROWS * DIMC];
__device__ float g_xr  [NQROWS * DIMC];        // tf32-rounded x
__device__ float g_htr [NTKROWS * DIMC];       // tf32-rounded h_t
__device__ float g_wr  [9][DIMC * DIMC];       // tf32-rounded weights

// ---------------- tf32 helpers ----------------
__device__ __forceinline__ float tf32r(float x) {
    uint32_t u;
    asm("cvt.rna.tf32.f32 %0, %1;" : "=r"(u) : "f"(x));
    return __uint_as_float(u);
}
__device__ __forceinline__ float4 tf32r4(float4 v) {
    return make_float4(tf32r(v.x), tf32r(v.y), tf32r(v.z), tf32r(v.w));
}

#define MMA_TF32(acc, a, b)                                                    \
    asm volatile(                                                              \
        "mma.sync.aligned.m16n8k8.row.col.f32.tf32.tf32.f32 "                  \
        "{%0,%1,%2,%3}, {%4,%5,%6,%7}, {%8,%9}, {%0,%1,%2,%3};\n"              \
        : "+f"((acc)[0]), "+f"((acc)[1]), "+f"((acc)[2]), "+f"((acc)[3])       \
        : "r"((a)[0]), "r"((a)[1]), "r"((a)[2]), "r"((a)[3]),                  \
          "r"((b)[0]), "r"((b)[1]))

__device__ __forceinline__ void cpa16(uint32_t dst, const float* src) {
    asm volatile("cp.async.cg.shared.global [%0], [%1], 16;\n"
                 :: "r"(dst), "l"(src));
}

// ---------------- pre-round pass: x, h_t, 9 weights -> tf32 ----------------
struct RoundArgs { const float* src[11]; float* dst[11]; };
__global__ __launch_bounds__(256)
void round_all(RoundArgs ra)
{
    int idx = blockIdx.x * 256 + threadIdx.x;    // float4 index
    int seg, off;
    if (idx < 1048576)      { seg = 0; off = idx; }                 // x: 4M floats
    else if (idx < 1572864) { seg = 1; off = idx - 1048576; }       // h_t: 2M
    else {
        int r = idx - 1572864;                                      // 9 x 1M
        seg = 2 + (r >> 18);
        off = r & 262143;
    }
    const float4* s = (const float4*)ra.src[seg];
    float4* d = (float4*)ra.dst[seg];
    d[off] = tf32r4(s[off]);
}

// ---------------- h_adapter = concat(h_a, p), tf32-rounded ----------------
__global__ void concat_kernel(const float* __restrict__ ha,
                              const float* __restrict__ pp,
                              float* __restrict__ out)
{
    int idx = blockIdx.x * blockDim.x + threadIdx.x;     // float4 index
    const int C4 = DIMC / 4;
    const int total = NADROWS * C4;
    if (idx >= total) return;
    int c4  = idx % C4;
    int row = idx / C4;
    int b = row / KADA;
    int s = row % KADA;
    float4 v;
    if (s < 256) v = ((const float4*)ha)[(size_t)(b * 256 + s) * C4 + c4];
    else         v = ((const float4*)pp)[(size_t)(b * 64 + (s - 256)) * C4 + c4];
    ((float4*)out)[idx] = tf32r4(v);
}

// ---------------- TF32 GEMM core: cp.async 3-stage pipeline ----------------
#define APITCH 20
#define BPITCH 136
#define A_STG  (128 * APITCH)   /* 2560 floats */
#define B_STG  (16 * BPITCH)    /* 2176 floats */
#define NSTG   3
#define GEMM_SMEM (NSTG * (A_STG + B_STG) * 4)   /* 56832 B */

__device__ __forceinline__ void gemm_body(
    const float* __restrict__ A, const float* __restrict__ W,
    const float* __restrict__ bias, const float* __restrict__ res,
    float* __restrict__ C, int K, int N, int rope_seq, int do_relu,
    int bm, int bn, int round_out, float* smem)
{
    float* smA = smem;
    float* smB = smem + NSTG * A_STG;

    const int tid  = threadIdx.x;
    const int lane = tid & 31, warp = tid >> 5;
    const int grp  = lane >> 2, tig = lane & 3;
    const int wm   = (warp >> 2) * 64;
    const int wn   = (warp & 3) * 32;

    const int arow0 = tid >> 2, ach = tid & 3;
    const int bk0   = tid >> 5;
    const int bn0   = (tid & 31) << 2;
    const float* Asrc0 = A + (size_t)(bm + arow0) * K + ach * 4;
    const float* Asrc1 = Asrc0 + (size_t)64 * K;
    const float* Bsrc0 = W + (size_t)bk0 * N + bn + bn0;
    const float* Bsrc1 = Bsrc0 + (size_t)8 * N;
    const uint32_t AdstBase = (uint32_t)__cvta_generic_to_shared(smA) + (arow0 * APITCH + ach * 4) * 4;
    const uint32_t BdstBase = (uint32_t)__cvta_generic_to_shared(smB) + (bk0 * BPITCH + bn0) * 4;
    const uint32_t Ad1 = 64 * APITCH * 4;
    const uint32_t Bd1 = 8 * BPITCH * 4;

#define G_ISSUE(sb, kk0) do {                                                  \
        uint32_t _ao = (uint32_t)(sb) * (A_STG * 4);                           \
        uint32_t _bo = (uint32_t)(sb) * (B_STG * 4);                           \
        cpa16(AdstBase + _ao,       Asrc0 + (kk0));                            \
        cpa16(AdstBase + _ao + Ad1, Asrc1 + (kk0));                            \
        cpa16(BdstBase + _bo,       Bsrc0 + (size_t)(kk0) * N);                \
        cpa16(BdstBase + _bo + Bd1, Bsrc1 + (size_t)(kk0) * N);                \
        asm volatile("cp.async.commit_group;\n" ::: "memory");                 \
    } while (0)

    float acc[4][4][4];
#pragma unroll
    for (int i = 0; i < 4; i++)
#pragma unroll
        for (int j = 0; j < 4; j++)
#pragma unroll
            for (int r = 0; r < 4; r++) acc[i][j][r] = 0.0f;

    const int NSLAB = K >> 4;
    G_ISSUE(0, 0);
    G_ISSUE(1, 16);

    int buf = 0;
    for (int i = 0; i < NSLAB; i++) {
        if (i == NSLAB - 1) asm volatile("cp.async.wait_group 0;\n" ::: "memory");
        else                asm volatile("cp.async.wait_group 1;\n" ::: "memory");
        __syncthreads();

        if (i + 2 < NSLAB) {
            int nbuf = buf + 2; if (nbuf >= 3) nbuf -= 3;
            G_ISSUE(nbuf, (i + 2) * 16);
        }

        const float* As = smA + buf * A_STG;
        const float* Bs = smB + buf * B_STG;
#pragma unroll
        for (int kk = 0; kk < 16; kk += 8) {
            uint32_t af[4][4], bf[4][2];
#pragma unroll
            for (int mi = 0; mi < 4; mi++) {
                const int m0 = wm + mi * 16 + grp;
                af[mi][0] = __float_as_uint(As[m0 * APITCH + kk + tig]);
                af[mi][1] = __float_as_uint(As[(m0 + 8) * APITCH + kk + tig]);
                af[mi][2] = __float_as_uint(As[m0 * APITCH + kk + tig + 4]);
                af[mi][3] = __float_as_uint(As[(m0 + 8) * APITCH + kk + tig + 4]);
            }
#pragma unroll
            for (int ni = 0; ni < 4; ni++) {
                const int n0 = wn + ni * 8 + grp;
                bf[ni][0] = __float_as_uint(Bs[(kk + tig) * BPITCH + n0]);
                bf[ni][1] = __float_as_uint(Bs[(kk + tig + 4) * BPITCH + n0]);
            }
#pragma unroll
            for (int mi = 0; mi < 4; mi++)
#pragma unroll
                for (int ni = 0; ni < 4; ni++)
                    MMA_TF32(acc[mi][ni], af[mi], bf[ni]);
        }
        buf++; if (buf == 3) buf = 0;
    }
#undef G_ISSUE

#pragma unroll
    for (int mi = 0; mi < 4; mi++) {
#pragma unroll
        for (int half = 0; half < 2; half++) {
            const int gRow = bm + wm + mi * 16 + grp + half * 8;
            const int pos = rope_seq ? (gRow % rope_seq) : 0;
            const float fp = (float)pos;
#pragma unroll
            for (int ni = 0; ni < 4; ni++) {
                const int gCol = bn + wn + ni * 8 + tig * 2;
                float v0 = acc[mi][ni][half * 2 + 0] + bias[gCol];
                float v1 = acc[mi][ni][half * 2 + 1] + bias[gCol + 1];
                if (res) {
                    const float* rr = res + (size_t)gRow * N + gCol;
                    v0 += rr[0];
                    v1 += rr[1];
                }
                if (rope_seq) {
                    const int d  = gCol & 63;
                    const int f0 = d & 31;
                    float inv0 = exp2f((float)f0       * -0.41524101186409203f);
                    float inv1 = exp2f((float)(f0 + 1) * -0.41524101186409203f);
                    float s0, c0, s1, c1;
                    sincosf(fp * inv0, &s0, &c0);
                    sincosf(fp * inv1, &s1, &c1);
                    float e = v0, o = v1;
                    v0 = e * c0 - o * s0;
                    v1 = o * c1 + e * s1;
                }
                if (do_relu) {
                    v0 = fmaxf(v0, 0.0f);
                    v1 = fmaxf(v1, 0.0f);
                }
                if (round_out) { v0 = tf32r(v0); v1 = tf32r(v1); }
                *(float2*)(C + (size_t)gRow * N + gCol) = make_float2(v0, v1);
            }
        }
    }
}

__global__ __launch_bounds__(256, 2)
void gemm_tf32_kernel(const float* __restrict__ A, const float* __restrict__ W,
                      const float* __restrict__ bias, const float* __restrict__ res,
                      float* __restrict__ C, int rope_seq, int do_relu)
{
    extern __shared__ float dynsm[];
    gemm_body(A, W, bias, res, C, DIMC, DIMC, rope_seq, do_relu,
              blockIdx.y * 128, blockIdx.x * 128, 0, dynsm);
}

struct G7 {
    const float* A[7]; const float* W[7]; const float* bias[7];
    float* C[7]; int rope[7]; int base[7];
};
__global__ __launch_bounds__(256, 2)
void gemm7_kernel(G7 g)
{
    extern __shared__ float dynsm[];
    const int bid = blockIdx.x;
    int seg = 0;
#pragma unroll
    for (int s = 1; s < 7; s++)
        if (bid >= g.base[s]) seg = s;
    const int loc = bid - g.base[seg];
    gemm_body(g.A[seg], g.W[seg], g.bias[seg], nullptr, g.C[seg],
              DIMC, DIMC, g.rope[seg], 0, (loc >> 3) * 128, (loc & 7) * 128,
              1, dynsm);
}

// ---------------- tensor-core flash attention, cp.async pipelined ----------------
// q-tile 64, 64-key tiles. 8 warps: 2(m:q32) x 4(n:16). K single-buffered,
// V double-buffered cp.async; prefetch of tile t+1 issued after Ss-write barrier.
// Inputs pre-rounded tf32; output tf32-rounded.
#define QP 68
#define KP 68
#define VP 72
#define SP 68
#define ATTN_SMEM_F (64 * QP + 64 * KP + 2 * 64 * VP + 64 * SP + 3 * 64)
__global__ __launch_bounds__(256, 2)
void attn_tc_kernel(const float* __restrict__ q,
                    const float* __restrict__ ktok, const float* __restrict__ vtok,
                    const float* __restrict__ kada, const float* __restrict__ vada,
                    const float* __restrict__ ktsk, const float* __restrict__ vtsk,
                    const float* __restrict__ gate, float* __restrict__ out)
{
    extern __shared__ float sm[];
    float* Qs   = sm;                 // [q][d]    64 x QP
    float* Ks   = Qs + 64 * QP;       // [key][d]  64 x KP (single buffer)
    float* Vs   = Ks + 64 * KP;       // [key][d]  2 x 64 x VP
    float* Ss   = Vs + 2 * 64 * VP;   // [q][key]  64 x SP
    float* sm_m = Ss + 64 * SP;       // 64
    float* sm_l = sm_m + 64;          // 64
    float* sm_a = sm_l + 64;          // 64

    const int b = blockIdx.z, h = blockIdx.y, qt = blockIdx.x;
    const int tid  = threadIdx.x;
    const int lane = tid & 31, warp = tid >> 5;
    const int grp  = lane >> 2, tig = lane & 3;
    const int wmq  = (warp & 1) * 32;    // q offset: 0/32
    const int wn   = (warp >> 1) * 16;   // key/d offset: 0,16,32,48
    const float gfac = tanhf(gate[0]);

    // cp.async mapping: 4 chunks per thread per tensor
    const int ldrow = tid >> 4, ldc4 = (tid & 15) << 2;   // +16 rows per iter
    const uint32_t KsB  = (uint32_t)__cvta_generic_to_shared(Ks) + (ldrow * KP + ldc4) * 4;
    const uint32_t VsB  = (uint32_t)__cvta_generic_to_shared(Vs) + (ldrow * VP + ldc4) * 4;
    const uint32_t VsD  = 64 * VP * 4;

#define TILE_PTRS(kt, kp, vp, sc) do {                                         \
        if ((kt) < 16) {                                                       \
            size_t off = ((size_t)(b * TQ + (kt) * 64)) * DIMC + h * HD;       \
            kp = ktok + off; vp = vtok + off; sc = 0.125f;                     \
        } else if ((kt) < 21) {                                                \
            size_t off = ((size_t)(b * KADA + ((kt) - 16) * 64)) * DIMC + h * HD; \
            kp = kada + off; vp = vada + off; sc = 0.125f;                     \
        } else {                                                               \
            size_t off = ((size_t)(b * KTSK + ((kt) - 21) * 64)) * DIMC + h * HD; \
            kp = ktsk + off; vp = vtsk + off; sc = 0.125f * gfac;              \
        }                                                                      \
    } while (0)

#define KV_ISSUE(kp, vp, vb) do {                                              \
        _Pragma("unroll")                                                      \
        for (int i = 0; i < 4; i++) {                                          \
            const int r = ldrow + i * 16;                                      \
            cpa16(KsB + i * 16 * KP * 4, (kp) + (size_t)r * DIMC + ldc4);      \
            cpa16(VsB + (uint32_t)(vb) * VsD + i * 16 * VP * 4,                \
                  (vp) + (size_t)r * DIMC + ldc4);                             \
        }                                                                      \
        asm volatile("cp.async.commit_group;\n" ::: "memory");                 \
    } while (0)

    // Q load (pre-rounded tf32): 64 x 64
    const float* qbase = q + ((size_t)(b * TQ + qt * 64)) * DIMC + h * HD;
    for (int f = tid; f < 1024; f += 256) {
        int r = f >> 4, d4 = (f & 15) << 2;
        *(float4*)&Qs[r * QP + d4] = *(const float4*)(qbase + (size_t)r * DIMC + d4);
    }
    if (tid < 64) { sm_m[tid] = -1e30f; sm_l[tid] = 0.0f; }

    // prologue: issue tile 0
    {
        const float *kp, *vp; float sc;
        TILE_PTRS(0, kp, vp, sc);
        KV_ISSUE(kp, vp, 0);
    }

    float oacc[2][2][4];
#pragma unroll
    for (int i = 0; i < 2; i++)
#pragma unroll
        for (int j = 0; j < 2; j++)
#pragma unroll
            for (int r = 0; r < 4; r++) oacc[i][j][r] = 0.0f;

    int vbuf = 0;
    float sscale;
    { const float *kp, *vp; TILE_PTRS(0, kp, vp, sscale); }

    for (int kt = 0; kt < NTILES; kt++) {
        asm volatile("cp.async.wait_group 0;\n" ::: "memory");
        __syncthreads();

        // ---- S = Q · K^T (m=64 q, n=64 keys, k=64 d) ----
        float sacc[2][2][4];
#pragma unroll
        for (int i = 0; i < 2; i++)
#pragma unroll
            for (int j = 0; j < 2; j++)
#pragma unroll
                for (int r = 0; r < 4; r++) sacc[i][j][r] = 0.0f;

#pragma unroll
        for (int kk = 0; kk < 64; kk += 8) {
            uint32_t af[2][4], bf[2][2];
#pragma unroll
            for (int mi = 0; mi < 2; mi++) {
                const int m0 = wmq + mi * 16 + grp;
                af[mi][0] = __float_as_uint(Qs[m0 * QP + kk + tig]);
                af[mi][1] = __float_as_uint(Qs[(m0 + 8) * QP + kk + tig]);
                af[mi][2] = __float_as_uint(Qs[m0 * QP + kk + tig + 4]);
                af[mi][3] = __float_as_uint(Qs[(m0 + 8) * QP + kk + tig + 4]);
            }
#pragma unroll
            for (int ni = 0; ni < 2; ni++) {
                const int n0 = wn + ni * 8 + grp;
                bf[ni][0] = __float_as_uint(Ks[n0 * KP + kk + tig]);
                bf[ni][1] = __float_as_uint(Ks[n0 * KP + kk + tig + 4]);
            }
#pragma unroll
            for (int mi = 0; mi < 2; mi++)
#pragma unroll
                for (int ni = 0; ni < 2; ni++)
                    MMA_TF32(sacc[mi][ni], af[mi], bf[ni]);
        }
#pragma unroll
        for (int mi = 0; mi < 2; mi++) {
            const int r0 = wmq + mi * 16 + grp;
#pragma unroll
            for (int ni = 0; ni < 2; ni++) {
                const int col = wn + ni * 8 + tig * 2;
                *(float2*)&Ss[r0 * SP + col] =
                    make_float2(sacc[mi][ni][0] * sscale, sacc[mi][ni][1] * sscale);
                *(float2*)&Ss[(r0 + 8) * SP + col] =
                    make_float2(sacc[mi][ni][2] * sscale, sacc[mi][ni][3] * sscale);
            }
        }
        __syncthreads();   // Ss visible; Ks fully consumed

        // issue tile kt+1 (K into single buffer; V into other buffer)
        if (kt + 1 < NTILES) {
            const float *kp, *vp; float scn;
            TILE_PTRS(kt + 1, kp, vp, scn);
            KV_ISSUE(kp, vp, vbuf ^ 1);
            sscale = scn;
        }

        // ---- online softmax: 4 lanes per q row, 16 keys each ----
        {
            const int qc = tid >> 2, part = tid & 3;
            float* srow = &Ss[qc * SP + part * 16];
            float lm = -1e30f;
#pragma unroll
            for (int k = 0; k < 16; k++) lm = fmaxf(lm, srow[k]);
            lm = fmaxf(lm, __shfl_xor_sync(0xffffffffu, lm, 1));
            lm = fmaxf(lm, __shfl_xor_sync(0xffffffffu, lm, 2));
            const float mold = sm_m[qc];
            const float mn = fmaxf(mold, lm);
            const float alpha = __expf(mold - mn);
            float lsum = 0.0f;
#pragma unroll
            for (int k = 0; k < 16; k++) {
                float pv = tf32r(__expf(srow[k] - mn));
                srow[k] = pv;
                lsum += pv;
            }
            lsum += __shfl_xor_sync(0xffffffffu, lsum, 1);
            lsum += __shfl_xor_sync(0xffffffffu, lsum, 2);
            if (part == 0) {
                sm_m[qc] = mn;
                sm_a[qc] = alpha;
                sm_l[qc] = sm_l[qc] * alpha + lsum;
            }
        }
        __syncthreads();

        // ---- O = O*alpha + P · V (m=64 q, n=64 d, k=64 keys) ----
        const float* Vb = Vs + vbuf * 64 * VP;
#pragma unroll
        for (int mi = 0; mi < 2; mi++) {
            const float a0 = sm_a[wmq + mi * 16 + grp];
            const float a1 = sm_a[wmq + mi * 16 + grp + 8];
#pragma unroll
            for (int ni = 0; ni < 2; ni++) {
                oacc[mi][ni][0] *= a0;
                oacc[mi][ni][1] *= a0;
                oacc[mi][ni][2] *= a1;
                oacc[mi][ni][3] *= a1;
            }
        }
#pragma unroll
        for (int kk = 0; kk < 64; kk += 8) {
            uint32_t af[2][4], bf[2][2];
#pragma unroll
            for (int mi = 0; mi < 2; mi++) {
                const int m0 = wmq + mi * 16 + grp;
                af[mi][0] = __float_as_uint(Ss[m0 * SP + kk + tig]);
                af[mi][1] = __float_as_uint(Ss[(m0 + 8) * SP + kk + tig]);
                af[mi][2] = __float_as_uint(Ss[m0 * SP + kk + tig + 4]);
                af[mi][3] = __float_as_uint(Ss[(m0 + 8) * SP + kk + tig + 4]);
            }
#pragma unroll
            for (int ni = 0; ni < 2; ni++) {
                const int n0 = wn + ni * 8 + grp;
                bf[ni][0] = __float_as_uint(Vb[(kk + tig) * VP + n0]);
                bf[ni][1] = __float_as_uint(Vb[(kk + tig + 4) * VP + n0]);
            }
#pragma unroll
            for (int mi = 0; mi < 2; mi++)
#pragma unroll
                for (int ni = 0; ni < 2; ni++)
                    MMA_TF32(oacc[mi][ni], af[mi], bf[ni]);
        }
        vbuf ^= 1;
        // next iteration's top wait+sync protects Ss/Ks reuse
    }
#undef KV_ISSUE
#undef TILE_PTRS

    // epilogue: normalize, round (feeds wo GEMM), write
    float* obase = out + ((size_t)(b * TQ + qt * 64)) * DIMC + h * HD;
#pragma unroll
    for (int mi = 0; mi < 2; mi++) {
        const int r0 = wmq + mi * 16 + grp;
        const float inv0 = 1.0f / sm_l[r0];
        const float inv1 = 1.0f / sm_l[r0 + 8];
#pragma unroll
        for (int ni = 0; ni < 2; ni++) {
            const int col = wn + ni * 8 + tig * 2;
            *(float2*)(obase + (size_t)r0 * DIMC + col) =
                make_float2(tf32r(oacc[mi][ni][0] * inv0), tf32r(oacc[mi][ni][1] * inv0));
            *(float2*)(obase + (size_t)(r0 + 8) * DIMC + col) =
                make_float2(tf32r(oacc[mi][ni][2] * inv1), tf32r(oacc[mi][ni][3] * inv1));
        }
    }
}

// ---------------- LayerNorm (output tf32-rounded; feeds wf GEMM) ----------------
__global__ __launch_bounds__(256)
void ln_kernel(const float* __restrict__ Y, const float* __restrict__ g,
               const float* __restrict__ bb, float* __restrict__ O)
{
    const int row = blockIdx.x;
    const int tid = threadIdx.x;
    const int c = tid * 4;
    float4 v = *(const float4*)(Y + (size_t)row * DIMC + c);
    float s  = v.x + v.y + v.z + v.w;
    float sq = v.x * v.x + v.y * v.y + v.z * v.z + v.w * v.w;
#pragma unroll
    for (int off = 16; off; off >>= 1) {
        s  += __shfl_xor_sync(0xffffffffu, s, off);
        sq += __shfl_xor_sync(0xffffffffu, sq, off);
    }
    __shared__ float ws[8], wsq[8];
    __shared__ float sh_mu, sh_r;
    const int w = tid >> 5, l = tid & 31;
    if (l == 0) { ws[w] = s; wsq[w] = sq; }
    __syncthreads();
    if (tid == 0) {
        float S = 0.0f, Q = 0.0f;
#pragma unroll
        for (int i = 0; i < 8; i++) { S += ws[i]; Q += wsq[i]; }
        float mu  = S / (float)DIMC;
        float var = Q / (float)DIMC - mu * mu;
        sh_mu = mu;
        sh_r  = rsqrtf(var + 1e-5f);
    }
    __syncthreads();
    const float mu = sh_mu, r = sh_r;
    float4 gg = *(const float4*)(g + c);
    float4 b4 = *(const float4*)(bb + c);
    float4 o4;
    o4.x = tf32r((v.x - mu) * r * gg.x + b4.x);
    o4.y = tf32r((v.y - mu) * r * gg.y + b4.y);
    o4.z = tf32r((v.z - mu) * r * gg.z + b4.z);
    o4.w = tf32r((v.w - mu) * r * gg.w + b4.w);
    *(float4*)(O + (size_t)row * DIMC + c) = o4;
}

// ---------------- launcher ----------------
extern "C" void kernel_launch(void* const* d_in, const int* in_sizes, int n_in,
                              void* d_out, int out_size)
{
    const float* x    = (const float*)d_in[0];
    const float* h_t  = (const float*)d_in[1];
    const float* h_a  = (const float*)d_in[2];
    const float* p    = (const float*)d_in[3];
    const float* wq   = (const float*)d_in[4];  const float* bq  = (const float*)d_in[5];
    const float* wks  = (const float*)d_in[6];  const float* bks = (const float*)d_in[7];
    const float* wvs  = (const float*)d_in[8];  const float* bvs = (const float*)d_in[9];
    const float* wka  = (const float*)d_in[10]; const float* bka = (const float*)d_in[11];
    const float* wva  = (const float*)d_in[12]; const float* bva = (const float*)d_in[13];
    const float* wkt  = (const float*)d_in[14]; const float* bkt = (const float*)d_in[15];
    const float* wvt  = (const float*)d_in[16]; const float* bvt = (const float*)d_in[17];
    const float* wo   = (const float*)d_in[18]; const float* bo  = (const float*)d_in[19];
    const float* wf   = (const float*)d_in[20]; const float* bf  = (const float*)d_in[21];
    const float* ln_g = (const float*)d_in[22];
    const float* ln_b = (const float*)d_in[23];
    const float* gate = (const float*)d_in[24];
    float* out = (float*)d_out;

    float *q_, *ktok_, *vtok_, *had_, *kada_, *vada_, *ktsk_, *vtsk_, *attn_, *y_, *yln_;
    float *xr_, *htr_, *wr_;
    cudaGetSymbolAddress((void**)&q_,    g_q);
    cudaGetSymbolAddress((void**)&ktok_, g_ktok);
    cudaGetSymbolAddress((void**)&vtok_, g_vtok);
    cudaGetSymbolAddress((void**)&had_,  g_had);
    cudaGetSymbolAddress((void**)&kada_, g_kada);
    cudaGetSymbolAddress((void**)&vada_, g_vada);
    cudaGetSymbolAddress((void**)&ktsk_, g_ktsk);
    cudaGetSymbolAddress((void**)&vtsk_, g_vtsk);
    cudaGetSymbolAddress((void**)&attn_, g_attn);
    cudaGetSymbolAddress((void**)&y_,    g_y);
    cudaGetSymbolAddress((void**)&yln_,  g_yln);
    cudaGetSymbolAddress((void**)&xr_,   g_xr);
    cudaGetSymbolAddress((void**)&htr_,  g_htr);
    cudaGetSymbolAddress((void**)&wr_,   g_wr);

    float* wrp[9];
    for (int i = 0; i < 9; i++) wrp[i] = wr_ + (size_t)i * DIMC * DIMC;

    const int ATTN_SMEM = ATTN_SMEM_F * 4;   // 89856 B -> 2 CTAs/SM
    cudaFuncSetAttribute(attn_tc_kernel, cudaFuncAttributeMaxDynamicSharedMemorySize, ATTN_SMEM);
    cudaFuncSetAttribute(gemm_tf32_kernel, cudaFuncAttributeMaxDynamicSharedMemorySize, GEMM_SMEM);
    cudaFuncSetAttribute(gemm7_kernel, cudaFuncAttributeMaxDynamicSharedMemorySize, GEMM_SMEM);

    // 1. pre-round x, h_t, 9 weights
    RoundArgs ra;
    ra.src[0] = x;    ra.dst[0] = xr_;
    ra.src[1] = h_t;  ra.dst[1] = htr_;
    const float* wsrc[9] = {wq, wks, wvs, wka, wva, wkt, wvt, wo, wf};
    for (int i = 0; i < 9; i++) { ra.src[2 + i] = wsrc[i]; ra.dst[2 + i] = wrp[i]; }
    round_all<<<15360, 256>>>(ra);

    // 2. h_adapter = concat(h_a, p) (rounded)
    concat_kernel<<<(NADROWS * DIMC / 4 + 255) / 256, 256>>>(h_a, p, had_);

    // 3. all 7 projections in one launch (outputs rounded post-rope)
    G7 g7;
    const float* As[7]   = {xr_, xr_, xr_, had_, had_, htr_, htr_};
    const float* Ws[7]   = {wrp[0], wrp[1], wrp[2], wrp[3], wrp[4], wrp[5], wrp[6]};
    const float* Bi[7]   = {bq, bks, bvs, bka, bva, bkt, bvt};
    float* Cs[7]         = {q_, ktok_, vtok_, kada_, vada_, ktsk_, vtsk_};
    const int ropes[7]   = {TQ, TQ, 0, KADA, 0, KTSK, 0};
    const int bases[7]   = {0, 256, 512, 768, 848, 928, 1056};
    for (int i = 0; i < 7; i++) {
        g7.A[i] = As[i]; g7.W[i] = Ws[i]; g7.bias[i] = Bi[i];
        g7.C[i] = Cs[i]; g7.rope[i] = ropes[i]; g7.base[i] = bases[i];
    }
    gemm7_kernel<<<1184, 256, GEMM_SMEM>>>(g7);

    // 4. attention (inputs pre-rounded; output rounded)
    dim3 ga(TQ / 64, HEADS, BATCH);   // (16, 16, 4) = 1024 CTAs
    attn_tc_kernel<<<ga, 256, ATTN_SMEM>>>(q_, ktok_, vtok_, kada_, vada_, ktsk_, vtsk_, gate, attn_);

    // 5. wo GEMM + residual (res = original fp32 x)
    dim3 g1(8, 32);
    gemm_tf32_kernel<<<g1, 256, GEMM_SMEM>>>(attn_, wrp[7], bo, x, y_, 0, 0);

    // 6. LayerNorm (output rounded)
    ln_kernel<<<NQROWS, 256>>>(y_, ln_g, ln_b, yln_);

    // 7. wf GEMM + ReLU -> out
    gemm_tf32_kernel<<<g1, 256, GEMM_SMEM>>>(yln_, wrp[8], bf, nullptr, out, 0, 1);
}